// round 10
// baseline (speedup 1.0000x reference)
#include <cuda_runtime.h>
#include <cuda_fp16.h>
#include <math.h>
#include <cstdint>

#define BB 4
#define NN 8192

// ---------------- device scratch ----------------
__device__ float g_tproj[BB*256];
__device__ float g_pbest[4*BB*NN];
__device__ int   g_pidx [4*BB*NN];
// fp16 weight planes: [N][128] u32 (2 f16/u32 along K), k-pairs permuted in 8-groups
// hi = f16(W);  lo = f16((W - hi)*2048)
__device__ uint32_t g_w1h[4*256*128], g_w1l[4*256*128];
__device__ uint32_t g_w2h[4*256*128], g_w2l[4*256*128];
__device__ uint32_t g_owh[128*128],   g_owl[128*128];

// ================= helpers =================
__device__ __forceinline__ uint32_t smem_to_u32(const void* p) {
    uint32_t a;
    asm("{ .reg .u64 t; cvta.to.shared.u64 t, %1; cvt.u32.u64 %0, t; }" : "=r"(a) : "l"(p));
    return a;
}
__device__ __forceinline__ void cp_async16(uint32_t d, const void* s) {
    asm volatile("cp.async.ca.shared.global [%0], [%1], 16;" :: "r"(d), "l"(s) : "memory");
}
#define CP_COMMIT() asm volatile("cp.async.commit_group;" ::: "memory")
template<int N> __device__ __forceinline__ void cp_wait() {
    asm volatile("cp.async.wait_group %0;" :: "n"(N) : "memory");
}
#define LD2(r0, r1, ba) asm volatile("ld.shared.v2.u32 {%0,%1}, [%2];" : "=r"(r0), "=r"(r1) : "r"(ba))

__device__ __forceinline__ uint32_t packh2(float x0, float x1) {
    uint32_t u;
    asm("cvt.rn.f16x2.f32 %0, %1, %2;" : "=r"(u) : "f"(x1), "f"(x0));
    return u;
}
__device__ __forceinline__ void mmaf16(float c[4], const uint32_t a[4], const uint32_t b[2]) {
    asm volatile(
        "mma.sync.aligned.m16n8k16.row.col.f32.f16.f16.f32 "
        "{%0,%1,%2,%3}, {%4,%5,%6,%7}, {%8,%9}, {%0,%1,%2,%3};"
        : "+f"(c[0]), "+f"(c[1]), "+f"(c[2]), "+f"(c[3])
        : "r"(a[0]), "r"(a[1]), "r"(a[2]), "r"(a[3]), "r"(b[0]), "r"(b[1]));
}
__device__ __forceinline__ float silu(float x) { return x / (1.0f + __expf(-x)); }
__device__ __forceinline__ int kperm(int p) {
    int l = p & 7;
    return (p & ~7) | ((l < 4) ? (l << 1) : (((l - 4) << 1) | 1));
}
#define INV2048 4.8828125e-4f

// smem float/u32 offsets (per-CTA 112,640 B -> 2 CTAs/SM)
#define O_XF    0        // fp32 residual 32 x 264
#define O_XH    8448     // act plane 32 x 136 u32
#define O_HH    12800    // h plane 32 x 136 u32
#define O_WB    17152    // single weight buffer 256 x 40 u32
#define O_SRS   27392    // 32 x 8
#define O_SRQ   27648
#define O_MU    27904
#define O_RS    27936
#define O_FEAT  27968    // 32 x 6
#define SMEM_F  28160
#define SMEM_BYTES (SMEM_F*4)

// ============ weight transpose + exact fp16 hi/lo split + k-pair perm ============
__global__ void splitw_kernel(const float* __restrict__ ly_w1,
                              const float* __restrict__ ly_w2,
                              const float* __restrict__ out_w1)
{
    __shared__ float ts[32][33];
    int m = blockIdx.x >> 6, tile = blockIdx.x & 63;
    const float* src; uint32_t *dh, *dl; int N = 256;
    if (m < 4)      { src = ly_w1 + m*65536;     dh = g_w1h + m*32768; dl = g_w1l + m*32768; }
    else if (m < 8) { src = ly_w2 + (m-4)*65536; dh = g_w2h + (m-4)*32768; dl = g_w2l + (m-4)*32768; }
    else            { src = out_w1;              dh = g_owh; dl = g_owl; N = 128; }
    int tn = (tile & 7) * 32, tk = (tile >> 3) * 32;
    if (tn >= N) return;
    int lx = threadIdx.x & 31, ly = threadIdx.x >> 5;
    #pragma unroll
    for (int i = 0; i < 32; i += 8) ts[ly+i][lx] = src[(tk+ly+i)*N + tn + lx];
    __syncthreads();
    int kk = lx & 15; bool ishi = lx < 16;
    int kkp = kperm(kk);
    #pragma unroll
    for (int i = 0; i < 32; i += 8) {
        int nl = ly + i;
        float x0 = ts[2*kk][nl], x1 = ts[2*kk+1][nl];
        __half2 hh = __floats2half2_rn(x0, x1);
        float h0 = __low2float(hh), h1 = __high2float(hh);
        __half2 llv = __floats2half2_rn((x0 - h0)*2048.f, (x1 - h1)*2048.f);
        int idx = (tn + nl)*128 + (tk >> 1) + kkp;
        if (ishi) dh[idx] = *reinterpret_cast<uint32_t*>(&hh);
        else      dl[idx] = *reinterpret_cast<uint32_t*>(&llv);
    }
}

// ============ time embedding ============
__global__ void temb_kernel(const int* __restrict__ timesteps,
                            const float* __restrict__ te_w1, const float* __restrict__ te_b1,
                            const float* __restrict__ te_w2, const float* __restrict__ te_b2,
                            const float* __restrict__ tp_w,  const float* __restrict__ tp_b)
{
    __shared__ float emb[128], h1[512], h2[512];
    int b = blockIdx.x, t = threadIdx.x;
    if (t < 64) {
        float fr = expf((float)t * (-logf(10000.0f) / 63.0f));
        float an = (float)timesteps[b] * fr;
        emb[t] = sinf(an); emb[t+64] = cosf(an);
    }
    __syncthreads();
    { float a = te_b1[t];
      #pragma unroll 4
      for (int k = 0; k < 128; k++) a = fmaf(emb[k], te_w1[k*512+t], a);
      h1[t] = a / (1.0f + expf(-a)); }
    __syncthreads();
    { float a = te_b2[t];
      #pragma unroll 4
      for (int k = 0; k < 512; k++) a = fmaf(h1[k], te_w2[k*512+t], a);
      h2[t] = a; }
    __syncthreads();
    if (t < 256) {
        float a = tp_b[t];
        #pragma unroll 4
        for (int k = 0; k < 512; k++) a = fmaf(h2[k], tp_w[k*256+t], a);
        g_tproj[b*256+t] = a;
    }
}

// ============ nearest neighbor ============
#define TSZ 2048
__global__ void nn_kernel(const float* __restrict__ noisy, const float* __restrict__ target)
{
    __shared__ float4 ts[TSZ];
    int b = blockIdx.x >> 8, chunk = (blockIdx.x >> 2) & 63, slice = blockIdx.x & 3;
    int t = threadIdx.x;
    const float4* tg4 = (const float4*)(target + ((size_t)b*NN + (size_t)slice*TSZ) * 3);
    for (int p4 = t; p4 < TSZ/4; p4 += 128) {
        float4 v0 = tg4[3*p4], v1 = tg4[3*p4+1], v2 = tg4[3*p4+2];
        ts[4*p4+0] = make_float4(v0.x, v0.y, v0.z, 0.5f*(v0.x*v0.x + v0.y*v0.y + v0.z*v0.z));
        ts[4*p4+1] = make_float4(v0.w, v1.x, v1.y, 0.5f*(v0.w*v0.w + v1.x*v1.x + v1.y*v1.y));
        ts[4*p4+2] = make_float4(v1.z, v1.w, v2.x, 0.5f*(v1.z*v1.z + v1.w*v1.w + v2.x*v2.x));
        ts[4*p4+3] = make_float4(v2.y, v2.z, v2.w, 0.5f*(v2.y*v2.y + v2.z*v2.z + v2.w*v2.w));
    }
    __syncthreads();
    int p = chunk*128 + t;
    const float* q = noisy + ((size_t)b*NN + p) * 3;
    float qx = -q[0], qy = -q[1], qz = -q[2];
    float best0 = INFINITY, best1 = INFINITY; int b0 = 0, b1 = 1;
    #pragma unroll 4
    for (int j = 0; j < TSZ; j += 2) {
        float4 v0 = ts[j], v1 = ts[j+1];
        float e0 = fmaf(qx, v0.x, v0.w); e0 = fmaf(qy, v0.y, e0); e0 = fmaf(qz, v0.z, e0);
        float e1 = fmaf(qx, v1.x, v1.w); e1 = fmaf(qy, v1.y, e1); e1 = fmaf(qz, v1.z, e1);
        if (e0 < best0) { best0 = e0; b0 = j; }
        if (e1 < best1) { best1 = e1; b1 = j+1; }
    }
    float best = best0; int bidx = b0;
    if (best1 < best0) { best = best1; bidx = b1; }
    int pi = b*NN + p;
    g_pbest[slice*(BB*NN) + pi] = best;
    g_pidx [slice*(BB*NN) + pi] = slice*TSZ + bidx;
}

// ============ fused fp16 weight-pair MLP, 256 thr, 2 CTA/SM ============
__device__ __forceinline__ void loadW(uint32_t* smu,
                                      const uint32_t* __restrict__ gh,
                                      const uint32_t* __restrict__ gl,
                                      int kc, int nRows, int t)
{
    uint32_t base = smem_to_u32(smu + O_WB);
    int tot = nRows*8;
    #pragma unroll
    for (int i = t; i < tot; i += 256) {
        int n = i >> 3, j = i & 7;
        if (j < 4) cp_async16(base + (uint32_t)((n*40 + j*4)*4),          gh + n*128 + kc*16 + j*4);
        else       cp_async16(base + (uint32_t)((n*40 + 16 + (j-4)*4)*4), gl + n*128 + kc*16 + (j-4)*4);
    }
}

// NT n8-tiles/warp: 4 => N=256 (8 n-warps), 2 => N=128. Single weight buffer.
template<int NT>
__device__ __forceinline__ void gemm_f16p(uint32_t* smu, uint32_t su, int Ao,
                                          const uint32_t* __restrict__ gh,
                                          const uint32_t* __restrict__ gl,
                                          int nRows, float ch[2][NT][4], float cl[2][NT][4],
                                          int t, int wn, int g, int tt)
{
    #pragma unroll 1
    for (int kc = 0; kc < 8; kc++) {
        __syncthreads();                       // prev tile consumed (kc=0: plane writes published)
        loadW(smu, gh, gl, kc, nRows, t);
        CP_COMMIT(); cp_wait<0>();
        __syncthreads();                       // tile kc visible
        uint32_t WB = su + (uint32_t)(O_WB*4);
        uint32_t a[2][2][4], bh[2][NT][2], bl[2][NT][2];
        #pragma unroll
        for (int ks = 0; ks < 2; ks++) {
            int cb = kc*16 + ks*8 + 2*tt;
            #pragma unroll
            for (int mi = 0; mi < 2; mi++) {
                int r = mi*16 + g;
                LD2(a[ks][mi][0], a[ks][mi][2], su + (uint32_t)((Ao + r*136 + cb)*4));
                LD2(a[ks][mi][1], a[ks][mi][3], su + (uint32_t)((Ao + (r+8)*136 + cb)*4));
            }
            #pragma unroll
            for (int nt = 0; nt < NT; nt++) {
                int n = wn*(NT*8) + nt*8 + g;
                uint32_t ib = WB + (uint32_t)((n*40 + ks*8 + 2*tt)*4);
                LD2(bh[ks][nt][0], bh[ks][nt][1], ib);
                LD2(bl[ks][nt][0], bl[ks][nt][1], ib + 64);
            }
        }
        #pragma unroll
        for (int ks = 0; ks < 2; ks++)
            #pragma unroll
            for (int mi = 0; mi < 2; mi++)
                #pragma unroll
                for (int nt = 0; nt < NT; nt++) {
                    mmaf16(ch[mi][nt], a[ks][mi], bh[ks][nt]);
                    mmaf16(cl[mi][nt], a[ks][mi], bl[ks][nt]);
                }
    }
    __syncthreads();
}

__global__ __launch_bounds__(256, 2)
void mlp_f16(const float* __restrict__ noisy, const float* __restrict__ target,
             const float* __restrict__ in_w,  const float* __restrict__ in_b,
             const float* __restrict__ ly_b1, const float* __restrict__ ly_g,
             const float* __restrict__ ly_be, const float* __restrict__ ly_b2,
             const float* __restrict__ out_b1, const float* __restrict__ out_w2,
             const float* __restrict__ out_b2, float* __restrict__ out)
{
    extern __shared__ float sm[];
    uint32_t* smu = (uint32_t*)sm;
    uint32_t su = smem_to_u32(sm);
    int t = threadIdx.x, lane = t & 31;
    int wn = t >> 5;                       // warp grid 1(M) x 8(N)
    int g = lane >> 2, tt = lane & 3;
    int b = blockIdx.x >> 8, row0 = (blockIdx.x & 255) << 5;

    float* xf   = sm + O_XF;
    float* feat = sm + O_FEAT;

    if (t < 32) {   // fused nn_reduce (32 rows)
        int pi = b*NN + row0 + t;
        float best = g_pbest[pi]; int bi = g_pidx[pi];
        #pragma unroll
        for (int s = 1; s < 4; s++) {
            float vv = g_pbest[s*(BB*NN) + pi];
            if (vv < best) { best = vv; bi = g_pidx[s*(BB*NN) + pi]; }
        }
        const float* tc = target + ((size_t)b*NN + bi)*3;
        feat[t*6+0] = noisy[(size_t)pi*3+0]; feat[t*6+1] = noisy[(size_t)pi*3+1]; feat[t*6+2] = noisy[(size_t)pi*3+2];
        feat[t*6+3] = tc[0]; feat[t*6+4] = tc[1]; feat[t*6+5] = tc[2];
    }
    __syncthreads();

    // ---- input build: x = feat @ in_w + (in_b + tproj) -> xf fp32 + XH plane ----
    {
        int row = t >> 3, q = t & 7;
        float f[6];
        #pragma unroll
        for (int k = 0; k < 6; k++) f[k] = feat[row*6 + k];
        const float* tp = g_tproj + b*256;
        #pragma unroll
        for (int c4 = 0; c4 < 8; c4++) {
            int col = q*32 + c4*4;
            float4 a  = *(const float4*)(in_b + col);
            float4 tv = *(const float4*)(tp + col);
            a.x += tv.x; a.y += tv.y; a.z += tv.z; a.w += tv.w;
            #pragma unroll
            for (int k = 0; k < 6; k++) {
                float4 wv = *(const float4*)(in_w + k*256 + col);
                a.x = fmaf(f[k], wv.x, a.x); a.y = fmaf(f[k], wv.y, a.y);
                a.z = fmaf(f[k], wv.z, a.z); a.w = fmaf(f[k], wv.w, a.w);
            }
            *(float4*)(xf + row*264 + col) = a;
            int p = col >> 1;
            smu[O_XH + row*136 + kperm(p)]   = packh2(a.x, a.y);
            smu[O_XH + row*136 + kperm(p+1)] = packh2(a.z, a.w);
        }
    }
    // gemm's first __syncthreads publishes plane writes

    float v[2][4][4];
    // ---- 4 residual layers ----
    #pragma unroll 1
    for (int lay = 0; lay < 4; lay++) {
        const float* b1p = ly_b1 + lay*256;
        const float* gap = ly_g  + lay*256;
        const float* bep = ly_be + lay*256;
        const float* b2p = ly_b2 + lay*256;

        // GEMM1: D = x @ W1
        float ch[2][4][4], cl[2][4][4];
        #pragma unroll
        for (int mi = 0; mi < 2; mi++)
            #pragma unroll
            for (int nt = 0; nt < 4; nt++)
                #pragma unroll
                for (int e = 0; e < 4; e++) { ch[mi][nt][e] = 0.f; cl[mi][nt][e] = 0.f; }
        gemm_f16p<4>(smu, su, O_XH, g_w1h + lay*32768, g_w1l + lay*32768, 256, ch, cl, t, wn, g, tt);

        // epilogue1: combine + b1, LN stats
        float S[2][2] = {{0,0},{0,0}}, Q[2][2] = {{0,0},{0,0}};
        #pragma unroll
        for (int mi = 0; mi < 2; mi++)
            #pragma unroll
            for (int nt = 0; nt < 4; nt++) {
                int bc = wn*32 + nt*8 + 2*tt;
                float b0 = b1p[bc], b1v = b1p[bc + 1];
                float v0 = fmaf(cl[mi][nt][0], INV2048, ch[mi][nt][0]) + b0;
                float v1 = fmaf(cl[mi][nt][1], INV2048, ch[mi][nt][1]) + b1v;
                float v2 = fmaf(cl[mi][nt][2], INV2048, ch[mi][nt][2]) + b0;
                float v3 = fmaf(cl[mi][nt][3], INV2048, ch[mi][nt][3]) + b1v;
                v[mi][nt][0]=v0; v[mi][nt][1]=v1; v[mi][nt][2]=v2; v[mi][nt][3]=v3;
                S[mi][0] += v0 + v1; Q[mi][0] = fmaf(v0,v0,fmaf(v1,v1,Q[mi][0]));
                S[mi][1] += v2 + v3; Q[mi][1] = fmaf(v2,v2,fmaf(v3,v3,Q[mi][1]));
            }
        #pragma unroll
        for (int mi = 0; mi < 2; mi++)
            #pragma unroll
            for (int h = 0; h < 2; h++) {
                float s = S[mi][h], q = Q[mi][h];
                s += __shfl_xor_sync(~0u, s, 1); s += __shfl_xor_sync(~0u, s, 2);
                q += __shfl_xor_sync(~0u, q, 1); q += __shfl_xor_sync(~0u, q, 2);
                if (tt == 0) {
                    int row = mi*16 + h*8 + g;
                    sm[O_SRS + row*8 + wn] = s;
                    sm[O_SRQ + row*8 + wn] = q;
                }
            }
        __syncthreads();
        if (t < 32) {
            float s = 0.f, q = 0.f;
            #pragma unroll
            for (int i = 0; i < 8; i++) { s += sm[O_SRS + t*8 + i]; q += sm[O_SRQ + t*8 + i]; }
            float mu = s * (1.f/256.f);
            sm[O_RS + t] = rsqrtf(fmaf(-mu, mu, q * (1.f/256.f)) + 1e-5f);
            sm[O_MU + t] = mu;
        }
        __syncthreads();
        // LN + SiLU -> h plane
        #pragma unroll
        for (int mi = 0; mi < 2; mi++)
            #pragma unroll
            for (int h = 0; h < 2; h++) {
                int row = mi*16 + h*8 + g;
                float mu = sm[O_MU + row], rs = sm[O_RS + row];
                #pragma unroll
                for (int nt = 0; nt < 4; nt++) {
                    int bc = wn*32 + nt*8 + 2*tt;
                    float h0 = silu(fmaf((v[mi][nt][2*h]   - mu)*rs, gap[bc],   bep[bc]));
                    float h1 = silu(fmaf((v[mi][nt][2*h+1] - mu)*rs, gap[bc+1], bep[bc+1]));
                    smu[O_HH + row*136 + kperm(bc >> 1)] = packh2(h0, h1);
                }
            }

        // GEMM2: D = h @ W2 (first sync publishes h writes)
        #pragma unroll
        for (int mi = 0; mi < 2; mi++)
            #pragma unroll
            for (int nt = 0; nt < 4; nt++)
                #pragma unroll
                for (int e = 0; e < 4; e++) { ch[mi][nt][e] = 0.f; cl[mi][nt][e] = 0.f; }
        gemm_f16p<4>(smu, su, O_HH, g_w2h + lay*32768, g_w2l + lay*32768, 256, ch, cl, t, wn, g, tt);

        // epilogue2: x(fp32) += D + b2; refresh act plane
        #pragma unroll
        for (int mi = 0; mi < 2; mi++)
            #pragma unroll
            for (int h = 0; h < 2; h++) {
                int row = mi*16 + h*8 + g;
                #pragma unroll
                for (int nt = 0; nt < 4; nt++) {
                    int bc = wn*32 + nt*8 + 2*tt;
                    float2* px = (float2*)(xf + row*264 + bc);
                    float2 xv = *px;
                    xv.x += fmaf(cl[mi][nt][2*h],   INV2048, ch[mi][nt][2*h])   + b2p[bc];
                    xv.y += fmaf(cl[mi][nt][2*h+1], INV2048, ch[mi][nt][2*h+1]) + b2p[bc + 1];
                    *px = xv;
                    smu[O_XH + row*136 + kperm(bc >> 1)] = packh2(xv.x, xv.y);
                }
            }
    }

    // ---- head GEMM: D = x @ out_w1 (N=128) ----
    {
        float ch[2][2][4], cl[2][2][4];
        #pragma unroll
        for (int mi = 0; mi < 2; mi++)
            #pragma unroll
            for (int nt = 0; nt < 2; nt++)
                #pragma unroll
                for (int e = 0; e < 4; e++) { ch[mi][nt][e] = 0.f; cl[mi][nt][e] = 0.f; }
        gemm_f16p<2>(smu, su, O_XH, g_owh, g_owl, 128, ch, cl, t, wn, g, tt);

        // y1 = silu(D + b1) -> fp32 [32][132] in XF region
        #pragma unroll
        for (int mi = 0; mi < 2; mi++)
            #pragma unroll
            for (int h = 0; h < 2; h++) {
                int row = mi*16 + h*8 + g;
                #pragma unroll
                for (int nt = 0; nt < 2; nt++) {
                    int bc = wn*16 + nt*8 + 2*tt;
                    float v0 = fmaf(cl[mi][nt][2*h],   INV2048, ch[mi][nt][2*h])   + out_b1[bc];
                    float v1 = fmaf(cl[mi][nt][2*h+1], INV2048, ch[mi][nt][2*h+1]) + out_b1[bc+1];
                    xf[row*132 + bc]     = silu(v0);
                    xf[row*132 + bc + 1] = silu(v1);
                }
            }
    }
    __syncthreads();

    // ---- final: score = y1 @ out_w2 + out_b2 (128 -> 3, fp32) ----
    if (t < 96) {
        int rr = t / 3, p = t - rr*3;
        float a = out_b2[p];
        const float* y = xf + rr*132;
        #pragma unroll 8
        for (int k = 0; k < 128; k++) a = fmaf(y[k], out_w2[k*3 + p], a);
        out[(size_t)((b*NN + row0 + rr)*3 + p)] = a;
    }
}

// =====================================================================
extern "C" void kernel_launch(void* const* d_in, const int* in_sizes, int n_in,
                              void* d_out, int out_size)
{
    const float* noisy  = (const float*)d_in[0];
    const float* target = (const float*)d_in[1];
    const int*   tsteps = (const int*)  d_in[2];
    const float* te_w1  = (const float*)d_in[3];
    const float* te_b1  = (const float*)d_in[4];
    const float* te_w2  = (const float*)d_in[5];
    const float* te_b2  = (const float*)d_in[6];
    const float* tp_w   = (const float*)d_in[7];
    const float* tp_b   = (const float*)d_in[8];
    const float* in_w   = (const float*)d_in[9];
    const float* in_b   = (const float*)d_in[10];
    const float* ly_w1  = (const float*)d_in[11];
    const float* ly_b1  = (const float*)d_in[12];
    const float* ly_g   = (const float*)d_in[13];
    const float* ly_be  = (const float*)d_in[14];
    const float* ly_w2  = (const float*)d_in[15];
    const float* ly_b2  = (const float*)d_in[16];
    const float* out_w1 = (const float*)d_in[17];
    const float* out_b1 = (const float*)d_in[18];
    const float* out_w2 = (const float*)d_in[19];
    const float* out_b2 = (const float*)d_in[20];
    float* out = (float*)d_out;

    cudaFuncSetAttribute(mlp_f16, cudaFuncAttributeMaxDynamicSharedMemorySize, SMEM_BYTES);

    splitw_kernel<<<576, 256>>>(ly_w1, ly_w2, out_w1);
    temb_kernel<<<4, 512>>>(tsteps, te_w1, te_b1, te_w2, te_b2, tp_w, tp_b);
    nn_kernel<<<1024, 128>>>(noisy, target);
    mlp_f16<<<1024, 256, SMEM_BYTES>>>(noisy, target, in_w, in_b,
                                       ly_b1, ly_g, ly_be, ly_b2,
                                       out_b1, out_w2, out_b2, out);
}

// round 11
// speedup vs baseline: 1.0915x; 1.0915x over previous
#include <cuda_runtime.h>
#include <cuda_fp16.h>
#include <math.h>
#include <cstdint>

#define BB 4
#define NN 8192

// ---------------- device scratch ----------------
__device__ float g_tproj[BB*256];
__device__ float g_pbest[4*BB*NN];
__device__ int   g_pidx [4*BB*NN];
// fp16 weight planes: [N][128] u32 (2 f16/u32 along K), k-pairs permuted in 8-groups
// hi = f16(W);  lo = f16((W - hi)*2048)
__device__ uint32_t g_w1h[4*256*128], g_w1l[4*256*128];
__device__ uint32_t g_w2h[4*256*128], g_w2l[4*256*128];
__device__ uint32_t g_owh[128*128],   g_owl[128*128];

// ================= helpers =================
__device__ __forceinline__ uint32_t smem_to_u32(const void* p) {
    uint32_t a;
    asm("{ .reg .u64 t; cvta.to.shared.u64 t, %1; cvt.u32.u64 %0, t; }" : "=r"(a) : "l"(p));
    return a;
}
__device__ __forceinline__ void cp_async16(uint32_t d, const void* s) {
    asm volatile("cp.async.ca.shared.global [%0], [%1], 16;" :: "r"(d), "l"(s) : "memory");
}
#define CP_COMMIT() asm volatile("cp.async.commit_group;" ::: "memory")
template<int N> __device__ __forceinline__ void cp_wait() {
    asm volatile("cp.async.wait_group %0;" :: "n"(N) : "memory");
}
#define LD2(r0, r1, ba) asm volatile("ld.shared.v2.u32 {%0,%1}, [%2];" : "=r"(r0), "=r"(r1) : "r"(ba))

__device__ __forceinline__ uint32_t packh2(float x0, float x1) {
    uint32_t u;
    asm("cvt.rn.f16x2.f32 %0, %1, %2;" : "=r"(u) : "f"(x1), "f"(x0));
    return u;
}
__device__ __forceinline__ void mmaf16(float c[4], const uint32_t a[4], const uint32_t b[2]) {
    asm volatile(
        "mma.sync.aligned.m16n8k16.row.col.f32.f16.f16.f32 "
        "{%0,%1,%2,%3}, {%4,%5,%6,%7}, {%8,%9}, {%0,%1,%2,%3};"
        : "+f"(c[0]), "+f"(c[1]), "+f"(c[2]), "+f"(c[3])
        : "r"(a[0]), "r"(a[1]), "r"(a[2]), "r"(a[3]), "r"(b[0]), "r"(b[1]));
}
__device__ __forceinline__ float silu(float x) { return x / (1.0f + __expf(-x)); }
__device__ __forceinline__ int kperm(int p) {
    int l = p & 7;
    return (p & ~7) | ((l < 4) ? (l << 1) : (((l - 4) << 1) | 1));
}
#define INV2048 4.8828125e-4f

// smem u32 offsets; per-CTA total 111,616 B -> 2 CTAs/SM
#define O_XH    0        // act plane 32 x 136 u32 (f16x2)
#define O_HH    4352     // h plane 32 x 136 u32; reused as fp32 y1 [32][132]
#define O_WB    8704     // 2 x (256 x 36 u32) weight double-buffer
#define O_SRS   27136    // 32 x 8 f
#define O_SRQ   27392
#define O_MU    27648
#define O_RS    27680
#define O_FEAT  27712    // 32 x 6 f
#define SMEM_U32 27904
#define SMEM_BYTES (SMEM_U32*4)

// ============ weight transpose + exact fp16 hi/lo split + k-pair perm ============
__global__ void splitw_kernel(const float* __restrict__ ly_w1,
                              const float* __restrict__ ly_w2,
                              const float* __restrict__ out_w1)
{
    __shared__ float ts[32][33];
    int m = blockIdx.x >> 6, tile = blockIdx.x & 63;
    const float* src; uint32_t *dh, *dl; int N = 256;
    if (m < 4)      { src = ly_w1 + m*65536;     dh = g_w1h + m*32768; dl = g_w1l + m*32768; }
    else if (m < 8) { src = ly_w2 + (m-4)*65536; dh = g_w2h + (m-4)*32768; dl = g_w2l + (m-4)*32768; }
    else            { src = out_w1;              dh = g_owh; dl = g_owl; N = 128; }
    int tn = (tile & 7) * 32, tk = (tile >> 3) * 32;
    if (tn >= N) return;
    int lx = threadIdx.x & 31, ly = threadIdx.x >> 5;
    #pragma unroll
    for (int i = 0; i < 32; i += 8) ts[ly+i][lx] = src[(tk+ly+i)*N + tn + lx];
    __syncthreads();
    int kk = lx & 15; bool ishi = lx < 16;
    int kkp = kperm(kk);
    #pragma unroll
    for (int i = 0; i < 32; i += 8) {
        int nl = ly + i;
        float x0 = ts[2*kk][nl], x1 = ts[2*kk+1][nl];
        __half2 hh = __floats2half2_rn(x0, x1);
        float h0 = __low2float(hh), h1 = __high2float(hh);
        __half2 llv = __floats2half2_rn((x0 - h0)*2048.f, (x1 - h1)*2048.f);
        int idx = (tn + nl)*128 + (tk >> 1) + kkp;
        if (ishi) dh[idx] = *reinterpret_cast<uint32_t*>(&hh);
        else      dl[idx] = *reinterpret_cast<uint32_t*>(&llv);
    }
}

// ============ time embedding ============
__global__ void temb_kernel(const int* __restrict__ timesteps,
                            const float* __restrict__ te_w1, const float* __restrict__ te_b1,
                            const float* __restrict__ te_w2, const float* __restrict__ te_b2,
                            const float* __restrict__ tp_w,  const float* __restrict__ tp_b)
{
    __shared__ float emb[128], h1[512], h2[512];
    int b = blockIdx.x, t = threadIdx.x;
    if (t < 64) {
        float fr = expf((float)t * (-logf(10000.0f) / 63.0f));
        float an = (float)timesteps[b] * fr;
        emb[t] = sinf(an); emb[t+64] = cosf(an);
    }
    __syncthreads();
    { float a = te_b1[t];
      #pragma unroll 4
      for (int k = 0; k < 128; k++) a = fmaf(emb[k], te_w1[k*512+t], a);
      h1[t] = a / (1.0f + expf(-a)); }
    __syncthreads();
    { float a = te_b2[t];
      #pragma unroll 4
      for (int k = 0; k < 512; k++) a = fmaf(h1[k], te_w2[k*512+t], a);
      h2[t] = a; }
    __syncthreads();
    if (t < 256) {
        float a = tp_b[t];
        #pragma unroll 4
        for (int k = 0; k < 512; k++) a = fmaf(h2[k], tp_w[k*256+t], a);
        g_tproj[b*256+t] = a;
    }
}

// ============ nearest neighbor ============
#define TSZ 2048
__global__ void nn_kernel(const float* __restrict__ noisy, const float* __restrict__ target)
{
    __shared__ float4 ts[TSZ];
    int b = blockIdx.x >> 8, chunk = (blockIdx.x >> 2) & 63, slice = blockIdx.x & 3;
    int t = threadIdx.x;
    const float4* tg4 = (const float4*)(target + ((size_t)b*NN + (size_t)slice*TSZ) * 3);
    for (int p4 = t; p4 < TSZ/4; p4 += 128) {
        float4 v0 = tg4[3*p4], v1 = tg4[3*p4+1], v2 = tg4[3*p4+2];
        ts[4*p4+0] = make_float4(v0.x, v0.y, v0.z, 0.5f*(v0.x*v0.x + v0.y*v0.y + v0.z*v0.z));
        ts[4*p4+1] = make_float4(v0.w, v1.x, v1.y, 0.5f*(v0.w*v0.w + v1.x*v1.x + v1.y*v1.y));
        ts[4*p4+2] = make_float4(v1.z, v1.w, v2.x, 0.5f*(v1.z*v1.z + v1.w*v1.w + v2.x*v2.x));
        ts[4*p4+3] = make_float4(v2.y, v2.z, v2.w, 0.5f*(v2.y*v2.y + v2.z*v2.z + v2.w*v2.w));
    }
    __syncthreads();
    int p = chunk*128 + t;
    const float* q = noisy + ((size_t)b*NN + p) * 3;
    float qx = -q[0], qy = -q[1], qz = -q[2];
    float best0 = INFINITY, best1 = INFINITY; int b0 = 0, b1 = 1;
    #pragma unroll 4
    for (int j = 0; j < TSZ; j += 2) {
        float4 v0 = ts[j], v1 = ts[j+1];
        float e0 = fmaf(qx, v0.x, v0.w); e0 = fmaf(qy, v0.y, e0); e0 = fmaf(qz, v0.z, e0);
        float e1 = fmaf(qx, v1.x, v1.w); e1 = fmaf(qy, v1.y, e1); e1 = fmaf(qz, v1.z, e1);
        if (e0 < best0) { best0 = e0; b0 = j; }
        if (e1 < best1) { best1 = e1; b1 = j+1; }
    }
    float best = best0; int bidx = b0;
    if (best1 < best0) { best = best1; bidx = b1; }
    int pi = b*NN + p;
    g_pbest[slice*(BB*NN) + pi] = best;
    g_pidx [slice*(BB*NN) + pi] = slice*TSZ + bidx;
}

// ============ fused fp16 weight-pair MLP, 256 thr, 2 CTA/SM, dbl-buf ============
__device__ __forceinline__ void loadW(uint32_t* smu, int buf,
                                      const uint32_t* __restrict__ gh,
                                      const uint32_t* __restrict__ gl,
                                      int kc, int nRows, int t)
{
    uint32_t base = smem_to_u32(smu + O_WB + buf*9216);
    int tot = nRows*8;
    #pragma unroll
    for (int i = t; i < tot; i += 256) {
        int n = i >> 3, j = i & 7;
        if (j < 4) cp_async16(base + (uint32_t)((n*36 + j*4)*4),          gh + n*128 + kc*16 + j*4);
        else       cp_async16(base + (uint32_t)((n*36 + 16 + (j-4)*4)*4), gl + n*128 + kc*16 + (j-4)*4);
    }
}

// NT n8-tiles/warp: 4 => N=256 (8 n-warps), 2 => N=128. Tile kc=0 pre-issued.
template<int NT>
__device__ __forceinline__ void gemm_f16p(uint32_t* smu, uint32_t su, int Ao,
                                          const uint32_t* __restrict__ gh,
                                          const uint32_t* __restrict__ gl,
                                          int nRows, float ch[2][NT][4], float cl[2][NT][4],
                                          int t, int wn, int g, int tt)
{
    #pragma unroll 1
    for (int kc = 0; kc < 8; kc++) {
        __syncthreads();                       // prev-buffer consumers done (kc=0: plane writes published)
        if (kc < 7) { loadW(smu, (kc+1)&1, gh, gl, kc+1, nRows, t); CP_COMMIT(); cp_wait<1>(); }
        else cp_wait<0>();
        __syncthreads();                       // tile kc visible
        uint32_t WB = su + (uint32_t)((O_WB + (kc&1)*9216)*4);
        uint32_t a[2][2][4], bh[2][NT][2], bl[2][NT][2];
        #pragma unroll
        for (int ks = 0; ks < 2; ks++) {
            int cb = kc*16 + ks*8 + 2*tt;
            #pragma unroll
            for (int mi = 0; mi < 2; mi++) {
                int r = mi*16 + g;
                LD2(a[ks][mi][0], a[ks][mi][2], su + (uint32_t)((Ao + r*136 + cb)*4));
                LD2(a[ks][mi][1], a[ks][mi][3], su + (uint32_t)((Ao + (r+8)*136 + cb)*4));
            }
            #pragma unroll
            for (int nt = 0; nt < NT; nt++) {
                int n = wn*(NT*8) + nt*8 + g;
                uint32_t ib = WB + (uint32_t)((n*36 + ks*8 + 2*tt)*4);
                LD2(bh[ks][nt][0], bh[ks][nt][1], ib);
                LD2(bl[ks][nt][0], bl[ks][nt][1], ib + 64);
            }
        }
        #pragma unroll
        for (int ks = 0; ks < 2; ks++)
            #pragma unroll
            for (int mi = 0; mi < 2; mi++)
                #pragma unroll
                for (int nt = 0; nt < NT; nt++) {
                    mmaf16(ch[mi][nt], a[ks][mi], bh[ks][nt]);
                    mmaf16(cl[mi][nt], a[ks][mi], bl[ks][nt]);
                }
    }
    __syncthreads();
}

__global__ __launch_bounds__(256, 2)
void mlp_f16(const float* __restrict__ noisy, const float* __restrict__ target,
             const float* __restrict__ in_w,  const float* __restrict__ in_b,
             const float* __restrict__ ly_b1, const float* __restrict__ ly_g,
             const float* __restrict__ ly_be, const float* __restrict__ ly_b2,
             const float* __restrict__ out_b1, const float* __restrict__ out_w2,
             const float* __restrict__ out_b2, float* __restrict__ out)
{
    extern __shared__ float sm[];
    uint32_t* smu = (uint32_t*)sm;
    uint32_t su = smem_to_u32(sm);
    int t = threadIdx.x, lane = t & 31;
    int wn = t >> 5;                       // warp grid 1(M) x 8(N)
    int g = lane >> 2, tt = lane & 3;
    int b = blockIdx.x >> 8, row0 = (blockIdx.x & 255) << 5;

    float* feat = sm + O_FEAT;

    if (t < 32) {   // fused nn_reduce (32 rows)
        int pi = b*NN + row0 + t;
        float best = g_pbest[pi]; int bi = g_pidx[pi];
        #pragma unroll
        for (int s = 1; s < 4; s++) {
            float vv = g_pbest[s*(BB*NN) + pi];
            if (vv < best) { best = vv; bi = g_pidx[s*(BB*NN) + pi]; }
        }
        const float* tc = target + ((size_t)b*NN + bi)*3;
        feat[t*6+0] = noisy[(size_t)pi*3+0]; feat[t*6+1] = noisy[(size_t)pi*3+1]; feat[t*6+2] = noisy[(size_t)pi*3+2];
        feat[t*6+3] = tc[0]; feat[t*6+4] = tc[1]; feat[t*6+5] = tc[2];
    }
    // pre-issue W1 layer0 tile0 (overlaps input build)
    loadW(smu, 0, g_w1h, g_w1l, 0, 256, t); CP_COMMIT();
    __syncthreads();

    // ---- input build in fragment layout: x = feat @ in_w + in_b + tproj ----
    // residual xr lives in REGISTERS: xr[mi][nt][e], e = h*2 + (col parity)
    float xr[2][4][4];
    {
        const float* tp = g_tproj + b*256;
        float fr[2][2][6];   // feat rows for (mi,h)
        #pragma unroll
        for (int mi = 0; mi < 2; mi++)
            #pragma unroll
            for (int h = 0; h < 2; h++) {
                int row = mi*16 + h*8 + g;
                #pragma unroll
                for (int k = 0; k < 6; k++) fr[mi][h][k] = feat[row*6 + k];
            }
        #pragma unroll
        for (int nt = 0; nt < 4; nt++) {
            int bc = wn*32 + nt*8 + 2*tt;
            #pragma unroll
            for (int half = 0; half < 2; half++) {
                int col = bc + half;
                float base = in_b[col] + tp[col];
                float w[6];
                #pragma unroll
                for (int k = 0; k < 6; k++) w[k] = in_w[k*256 + col];
                #pragma unroll
                for (int mi = 0; mi < 2; mi++)
                    #pragma unroll
                    for (int h = 0; h < 2; h++) {
                        float a = base;
                        #pragma unroll
                        for (int k = 0; k < 6; k++) a = fmaf(fr[mi][h][k], w[k], a);
                        xr[mi][nt][h*2 + half] = a;
                    }
            }
            // store act plane (f16 pairs)
            #pragma unroll
            for (int mi = 0; mi < 2; mi++)
                #pragma unroll
                for (int h = 0; h < 2; h++) {
                    int row = mi*16 + h*8 + g;
                    smu[O_XH + row*136 + kperm(bc >> 1)] = packh2(xr[mi][nt][h*2], xr[mi][nt][h*2+1]);
                }
        }
    }
    // gemm's first __syncthreads publishes plane writes

    // ---- 4 residual layers ----
    #pragma unroll 1
    for (int lay = 0; lay < 4; lay++) {
        const float* b1p = ly_b1 + lay*256;
        const float* gap = ly_g  + lay*256;
        const float* bep = ly_be + lay*256;
        const float* b2p = ly_b2 + lay*256;

        // GEMM1: D = x @ W1
        float ch[2][4][4], cl[2][4][4];
        #pragma unroll
        for (int mi = 0; mi < 2; mi++)
            #pragma unroll
            for (int nt = 0; nt < 4; nt++)
                #pragma unroll
                for (int e = 0; e < 4; e++) { ch[mi][nt][e] = 0.f; cl[mi][nt][e] = 0.f; }
        gemm_f16p<4>(smu, su, O_XH, g_w1h + lay*32768, g_w1l + lay*32768, 256, ch, cl, t, wn, g, tt);

        // pre-issue GEMM2 tile0 (overlaps epilogue1)
        loadW(smu, 0, g_w2h + lay*32768, g_w2l + lay*32768, 0, 256, t); CP_COMMIT();

        // epilogue1: combine into ch (v = ch + cl/2048 + b1), LN stats
        float S[2][2] = {{0,0},{0,0}}, Q[2][2] = {{0,0},{0,0}};
        #pragma unroll
        for (int mi = 0; mi < 2; mi++)
            #pragma unroll
            for (int nt = 0; nt < 4; nt++) {
                int bc = wn*32 + nt*8 + 2*tt;
                float b0 = b1p[bc], b1v = b1p[bc + 1];
                float v0 = fmaf(cl[mi][nt][0], INV2048, ch[mi][nt][0]) + b0;
                float v1 = fmaf(cl[mi][nt][1], INV2048, ch[mi][nt][1]) + b1v;
                float v2 = fmaf(cl[mi][nt][2], INV2048, ch[mi][nt][2]) + b0;
                float v3 = fmaf(cl[mi][nt][3], INV2048, ch[mi][nt][3]) + b1v;
                ch[mi][nt][0]=v0; ch[mi][nt][1]=v1; ch[mi][nt][2]=v2; ch[mi][nt][3]=v3;
                S[mi][0] += v0 + v1; Q[mi][0] = fmaf(v0,v0,fmaf(v1,v1,Q[mi][0]));
                S[mi][1] += v2 + v3; Q[mi][1] = fmaf(v2,v2,fmaf(v3,v3,Q[mi][1]));
            }
        #pragma unroll
        for (int mi = 0; mi < 2; mi++)
            #pragma unroll
            for (int h = 0; h < 2; h++) {
                float s = S[mi][h], q = Q[mi][h];
                s += __shfl_xor_sync(~0u, s, 1); s += __shfl_xor_sync(~0u, s, 2);
                q += __shfl_xor_sync(~0u, q, 1); q += __shfl_xor_sync(~0u, q, 2);
                if (tt == 0) {
                    int row = mi*16 + h*8 + g;
                    sm[O_SRS + row*8 + wn] = s;
                    sm[O_SRQ + row*8 + wn] = q;
                }
            }
        __syncthreads();
        if (t < 32) {
            float s = 0.f, q = 0.f;
            #pragma unroll
            for (int i = 0; i < 8; i++) { s += sm[O_SRS + t*8 + i]; q += sm[O_SRQ + t*8 + i]; }
            float mu = s * (1.f/256.f);
            sm[O_RS + t] = rsqrtf(fmaf(-mu, mu, q * (1.f/256.f)) + 1e-5f);
            sm[O_MU + t] = mu;
        }
        __syncthreads();
        // LN + SiLU -> h plane
        #pragma unroll
        for (int mi = 0; mi < 2; mi++)
            #pragma unroll
            for (int h = 0; h < 2; h++) {
                int row = mi*16 + h*8 + g;
                float mu = sm[O_MU + row], rs = sm[O_RS + row];
                #pragma unroll
                for (int nt = 0; nt < 4; nt++) {
                    int bc = wn*32 + nt*8 + 2*tt;
                    float h0 = silu(fmaf((ch[mi][nt][2*h]   - mu)*rs, gap[bc],   bep[bc]));
                    float h1 = silu(fmaf((ch[mi][nt][2*h+1] - mu)*rs, gap[bc+1], bep[bc+1]));
                    smu[O_HH + row*136 + kperm(bc >> 1)] = packh2(h0, h1);
                }
            }

        // GEMM2: D = h @ W2 (tile0 pre-issued; first sync publishes h writes)
        #pragma unroll
        for (int mi = 0; mi < 2; mi++)
            #pragma unroll
            for (int nt = 0; nt < 4; nt++)
                #pragma unroll
                for (int e = 0; e < 4; e++) { ch[mi][nt][e] = 0.f; cl[mi][nt][e] = 0.f; }
        gemm_f16p<4>(smu, su, O_HH, g_w2h + lay*32768, g_w2l + lay*32768, 256, ch, cl, t, wn, g, tt);

        // pre-issue next tile0 (next W1 or head) — overlaps epilogue2
        if (lay < 3) loadW(smu, 0, g_w1h + (lay+1)*32768, g_w1l + (lay+1)*32768, 0, 256, t);
        else         loadW(smu, 0, g_owh, g_owl, 0, 128, t);
        CP_COMMIT();

        // epilogue2: xr(regs) += D + b2; refresh act plane
        #pragma unroll
        for (int mi = 0; mi < 2; mi++)
            #pragma unroll
            for (int h = 0; h < 2; h++) {
                int row = mi*16 + h*8 + g;
                #pragma unroll
                for (int nt = 0; nt < 4; nt++) {
                    int bc = wn*32 + nt*8 + 2*tt;
                    float x0 = xr[mi][nt][2*h]   + fmaf(cl[mi][nt][2*h],   INV2048, ch[mi][nt][2*h])   + b2p[bc];
                    float x1 = xr[mi][nt][2*h+1] + fmaf(cl[mi][nt][2*h+1], INV2048, ch[mi][nt][2*h+1]) + b2p[bc + 1];
                    xr[mi][nt][2*h] = x0; xr[mi][nt][2*h+1] = x1;
                    smu[O_XH + row*136 + kperm(bc >> 1)] = packh2(x0, x1);
                }
            }
    }

    // ---- head GEMM: D = x @ out_w1 (N=128, tile0 pre-issued) ----
    {
        float ch[2][2][4], cl[2][2][4];
        #pragma unroll
        for (int mi = 0; mi < 2; mi++)
            #pragma unroll
            for (int nt = 0; nt < 2; nt++)
                #pragma unroll
                for (int e = 0; e < 4; e++) { ch[mi][nt][e] = 0.f; cl[mi][nt][e] = 0.f; }
        gemm_f16p<2>(smu, su, O_XH, g_owh, g_owl, 128, ch, cl, t, wn, g, tt);

        // y1 = silu(D + b1) -> fp32 [32][132] in HH region
        float* y1f = sm + O_HH;
        #pragma unroll
        for (int mi = 0; mi < 2; mi++)
            #pragma unroll
            for (int h = 0; h < 2; h++) {
                int row = mi*16 + h*8 + g;
                #pragma unroll
                for (int nt = 0; nt < 2; nt++) {
                    int bc = wn*16 + nt*8 + 2*tt;
                    float v0 = fmaf(cl[mi][nt][2*h],   INV2048, ch[mi][nt][2*h])   + out_b1[bc];
                    float v1 = fmaf(cl[mi][nt][2*h+1], INV2048, ch[mi][nt][2*h+1]) + out_b1[bc+1];
                    y1f[row*132 + bc]     = silu(v0);
                    y1f[row*132 + bc + 1] = silu(v1);
                }
            }
    }
    __syncthreads();

    // ---- final: score = y1 @ out_w2 + out_b2 (128 -> 3, fp32) ----
    if (t < 96) {
        int rr = t / 3, p = t - rr*3;
        float a = out_b2[p];
        const float* y = sm + O_HH + rr*132;
        #pragma unroll 8
        for (int k = 0; k < 128; k++) a = fmaf(y[k], out_w2[k*3 + p], a);
        out[(size_t)((b*NN + row0 + rr)*3 + p)] = a;
    }
}

// =====================================================================
extern "C" void kernel_launch(void* const* d_in, const int* in_sizes, int n_in,
                              void* d_out, int out_size)
{
    const float* noisy  = (const float*)d_in[0];
    const float* target = (const float*)d_in[1];
    const int*   tsteps = (const int*)  d_in[2];
    const float* te_w1  = (const float*)d_in[3];
    const float* te_b1  = (const float*)d_in[4];
    const float* te_w2  = (const float*)d_in[5];
    const float* te_b2  = (const float*)d_in[6];
    const float* tp_w   = (const float*)d_in[7];
    const float* tp_b   = (const float*)d_in[8];
    const float* in_w   = (const float*)d_in[9];
    const float* in_b   = (const float*)d_in[10];
    const float* ly_w1  = (const float*)d_in[11];
    const float* ly_b1  = (const float*)d_in[12];
    const float* ly_g   = (const float*)d_in[13];
    const float* ly_be  = (const float*)d_in[14];
    const float* ly_w2  = (const float*)d_in[15];
    const float* ly_b2  = (const float*)d_in[16];
    const float* out_w1 = (const float*)d_in[17];
    const float* out_b1 = (const float*)d_in[18];
    const float* out_w2 = (const float*)d_in[19];
    const float* out_b2 = (const float*)d_in[20];
    float* out = (float*)d_out;

    cudaFuncSetAttribute(mlp_f16, cudaFuncAttributeMaxDynamicSharedMemorySize, SMEM_BYTES);

    splitw_kernel<<<576, 256>>>(ly_w1, ly_w2, out_w1);
    temb_kernel<<<4, 512>>>(tsteps, te_w1, te_b1, te_w2, te_b2, tp_w, tp_b);
    nn_kernel<<<1024, 128>>>(noisy, target);
    mlp_f16<<<1024, 256, SMEM_BYTES>>>(noisy, target, in_w, in_b,
                                       ly_b1, ly_g, ly_be, ly_b2,
                                       out_b1, out_w2, out_b2, out);
}

// round 12
// speedup vs baseline: 1.0965x; 1.0046x over previous
#include <cuda_runtime.h>
#include <cuda_fp16.h>
#include <math.h>
#include <cstdint>

#define BB 4
#define NN 8192

// ---------------- device scratch ----------------
__device__ float g_tproj[BB*256];
__device__ float g_pbest[4*BB*NN];
__device__ int   g_pidx [4*BB*NN];
// fp16 weight planes: [N][128] u32 (2 f16/u32 along K), k-pairs M-permuted within 16-groups
// hi = f16(W);  lo = f16((W - hi)*2048)
__device__ uint32_t g_w1h[4*256*128], g_w1l[4*256*128];
__device__ uint32_t g_w2h[4*256*128], g_w2l[4*256*128];
__device__ uint32_t g_owh[128*128],   g_owl[128*128];

// ================= helpers =================
__device__ __forceinline__ uint32_t smem_to_u32(const void* p) {
    uint32_t a;
    asm("{ .reg .u64 t; cvta.to.shared.u64 t, %1; cvt.u32.u64 %0, t; }" : "=r"(a) : "l"(p));
    return a;
}
__device__ __forceinline__ void cp_async16(uint32_t d, const void* s) {
    asm volatile("cp.async.ca.shared.global [%0], [%1], 16;" :: "r"(d), "l"(s) : "memory");
}
#define CP_COMMIT() asm volatile("cp.async.commit_group;" ::: "memory")
template<int N> __device__ __forceinline__ void cp_wait() {
    asm volatile("cp.async.wait_group %0;" :: "n"(N) : "memory");
}
#define LD4(r0,r1,r2,r3,ba) asm volatile("ld.shared.v4.u32 {%0,%1,%2,%3}, [%4];" \
    : "=r"(r0),"=r"(r1),"=r"(r2),"=r"(r3) : "r"(ba))
#define ST4(ba,r0,r1,r2,r3) asm volatile("st.shared.v4.b32 [%0], {%1,%2,%3,%4};" \
    :: "r"(ba),"r"(r0),"r"(r1),"r"(r2),"r"(r3) : "memory")

__device__ __forceinline__ uint32_t packh2(float x0, float x1) {
    uint32_t u;
    asm("cvt.rn.f16x2.f32 %0, %1, %2;" : "=r"(u) : "f"(x1), "f"(x0));
    return u;
}
__device__ __forceinline__ void mmaf16(float c[4], const uint32_t a[4], const uint32_t b[2]) {
    asm volatile(
        "mma.sync.aligned.m16n8k16.row.col.f32.f16.f16.f32 "
        "{%0,%1,%2,%3}, {%4,%5,%6,%7}, {%8,%9}, {%0,%1,%2,%3};"
        : "+f"(c[0]), "+f"(c[1]), "+f"(c[2]), "+f"(c[3])
        : "r"(a[0]), "r"(a[1]), "r"(a[2]), "r"(a[3]), "r"(b[0]), "r"(b[1]));
}
__device__ __forceinline__ float silu(float x) { return x / (1.0f + __expf(-x)); }
#define INV2048 4.8828125e-4f

// smem u32 offsets; per-CTA total 105,472 B -> 2 CTAs/SM
// act/h planes: 32 rows x 144 u32 (128 used + 16 pad; row stride 576B = 64 mod 128 -> LDS.128 conflict-free)
#define O_XH    0        // 4608
#define O_HH    4608     // 4608; reused as fp32 y1 [32][132]
#define O_WB    9216     // 2 x 8192 u32 weight buffers (per-8-row 1024B chunk blocks)
#define O_SRS   25600    // 32 x 8 f
#define O_SRQ   25856
#define O_MU    26112
#define O_RS    26144
#define O_FEAT  26176    // 32 x 6 f
#define SMEM_U32 26368
#define SMEM_BYTES (SMEM_U32*4)

// ============ weight transpose + exact fp16 hi/lo split + M-perm ============
__global__ void splitw_kernel(const float* __restrict__ ly_w1,
                              const float* __restrict__ ly_w2,
                              const float* __restrict__ out_w1)
{
    __shared__ float ts[32][33];
    int m = blockIdx.x >> 6, tile = blockIdx.x & 63;
    const float* src; uint32_t *dh, *dl; int N = 256;
    if (m < 4)      { src = ly_w1 + m*65536;     dh = g_w1h + m*32768; dl = g_w1l + m*32768; }
    else if (m < 8) { src = ly_w2 + (m-4)*65536; dh = g_w2h + (m-4)*32768; dl = g_w2l + (m-4)*32768; }
    else            { src = out_w1;              dh = g_owh; dl = g_owl; N = 128; }
    int tn = (tile & 7) * 32, tk = (tile >> 3) * 32;   // one 32-k tile = one 16-pair group
    if (tn >= N) return;
    int lx = threadIdx.x & 31, ly = threadIdx.x >> 5;
    #pragma unroll
    for (int i = 0; i < 32; i += 8) ts[ly+i][lx] = src[(tk+ly+i)*N + tn + lx];
    __syncthreads();
    int kk = lx & 15; bool ishi = lx < 16;
    int pos = ((kk & 3) << 2) | (kk >> 2);             // M-perm: transpose within 16
    #pragma unroll
    for (int i = 0; i < 32; i += 8) {
        int nl = ly + i;
        float x0 = ts[2*kk][nl], x1 = ts[2*kk+1][nl];
        __half2 hh = __floats2half2_rn(x0, x1);
        float h0 = __low2float(hh), h1 = __high2float(hh);
        __half2 llv = __floats2half2_rn((x0 - h0)*2048.f, (x1 - h1)*2048.f);
        int idx = (tn + nl)*128 + (tk >> 1) + pos;
        if (ishi) dh[idx] = *reinterpret_cast<uint32_t*>(&hh);
        else      dl[idx] = *reinterpret_cast<uint32_t*>(&llv);
    }
}

// ============ time embedding ============
__global__ void temb_kernel(const int* __restrict__ timesteps,
                            const float* __restrict__ te_w1, const float* __restrict__ te_b1,
                            const float* __restrict__ te_w2, const float* __restrict__ te_b2,
                            const float* __restrict__ tp_w,  const float* __restrict__ tp_b)
{
    __shared__ float emb[128], h1[512], h2[512];
    int b = blockIdx.x, t = threadIdx.x;
    if (t < 64) {
        float fr = expf((float)t * (-logf(10000.0f) / 63.0f));
        float an = (float)timesteps[b] * fr;
        emb[t] = sinf(an); emb[t+64] = cosf(an);
    }
    __syncthreads();
    { float a = te_b1[t];
      #pragma unroll 4
      for (int k = 0; k < 128; k++) a = fmaf(emb[k], te_w1[k*512+t], a);
      h1[t] = a / (1.0f + expf(-a)); }
    __syncthreads();
    { float a = te_b2[t];
      #pragma unroll 4
      for (int k = 0; k < 512; k++) a = fmaf(h1[k], te_w2[k*512+t], a);
      h2[t] = a; }
    __syncthreads();
    if (t < 256) {
        float a = tp_b[t];
        #pragma unroll 4
        for (int k = 0; k < 512; k++) a = fmaf(h2[k], tp_w[k*256+t], a);
        g_tproj[b*256+t] = a;
    }
}

// ============ nearest neighbor ============
#define TSZ 2048
__global__ void nn_kernel(const float* __restrict__ noisy, const float* __restrict__ target)
{
    __shared__ float4 ts[TSZ];
    int b = blockIdx.x >> 8, chunk = (blockIdx.x >> 2) & 63, slice = blockIdx.x & 3;
    int t = threadIdx.x;
    const float4* tg4 = (const float4*)(target + ((size_t)b*NN + (size_t)slice*TSZ) * 3);
    for (int p4 = t; p4 < TSZ/4; p4 += 128) {
        float4 v0 = tg4[3*p4], v1 = tg4[3*p4+1], v2 = tg4[3*p4+2];
        ts[4*p4+0] = make_float4(v0.x, v0.y, v0.z, 0.5f*(v0.x*v0.x + v0.y*v0.y + v0.z*v0.z));
        ts[4*p4+1] = make_float4(v0.w, v1.x, v1.y, 0.5f*(v0.w*v0.w + v1.x*v1.x + v1.y*v1.y));
        ts[4*p4+2] = make_float4(v1.z, v1.w, v2.x, 0.5f*(v1.z*v1.z + v1.w*v1.w + v2.x*v2.x));
        ts[4*p4+3] = make_float4(v2.y, v2.z, v2.w, 0.5f*(v2.y*v2.y + v2.z*v2.z + v2.w*v2.w));
    }
    __syncthreads();
    int p = chunk*128 + t;
    const float* q = noisy + ((size_t)b*NN + p) * 3;
    float qx = -q[0], qy = -q[1], qz = -q[2];
    float best0 = INFINITY, best1 = INFINITY; int b0 = 0, b1 = 1;
    #pragma unroll 4
    for (int j = 0; j < TSZ; j += 2) {
        float4 v0 = ts[j], v1 = ts[j+1];
        float e0 = fmaf(qx, v0.x, v0.w); e0 = fmaf(qy, v0.y, e0); e0 = fmaf(qz, v0.z, e0);
        float e1 = fmaf(qx, v1.x, v1.w); e1 = fmaf(qy, v1.y, e1); e1 = fmaf(qz, v1.z, e1);
        if (e0 < best0) { best0 = e0; b0 = j; }
        if (e1 < best1) { best1 = e1; b1 = j+1; }
    }
    float best = best0; int bidx = b0;
    if (best1 < best0) { best = best1; bidx = b1; }
    int pi = b*NN + p;
    g_pbest[slice*(BB*NN) + pi] = best;
    g_pidx [slice*(BB*NN) + pi] = slice*TSZ + bidx;
}

// ============ fused fp16 weight-pair MLP, 256 thr, 2 CTA/SM, dbl-buf ============
// weight smem layout: per 8-row group nb: 1024B block = [hi: 32 chunks of 16B by (g*4+tt)][lo: +512B]
__device__ __forceinline__ void loadW(uint32_t buf /*byte addr*/,
                                      const uint32_t* __restrict__ gh,
                                      const uint32_t* __restrict__ gl,
                                      int kc, int nRows, int t)
{
    int n0 = t >> 2, tt = t & 3;
    uint32_t d = buf + (uint32_t)((n0 >> 3)*1024 + ((n0 & 7)*4 + tt)*16);
    const uint32_t* sh = gh + n0*128 + kc*16 + tt*4;
    const uint32_t* sl = gl + n0*128 + kc*16 + tt*4;
    int kmax = nRows >> 6;
    #pragma unroll
    for (int k = 0; k < kmax; k++) {
        cp_async16(d + (uint32_t)(k*8192),       sh + k*8192);
        cp_async16(d + (uint32_t)(k*8192 + 512), sl + k*8192);
    }
}

// NT n8-tiles/warp: 4 => N=256 (8 n-warps), 2 => N=128. Tile kc=0 pre-issued.
template<int NT>
__device__ __forceinline__ void gemm_f16p(uint32_t su, int Ao,
                                          const uint32_t* __restrict__ gh,
                                          const uint32_t* __restrict__ gl,
                                          int nRows, float ch[2][NT][4], float cl[2][NT][4],
                                          int t, int wn, int g, int tt)
{
    uint32_t WB0 = su + (uint32_t)(O_WB*4);
    #pragma unroll 1
    for (int kc = 0; kc < 8; kc++) {
        __syncthreads();                       // prev-buffer consumers done (kc=0: plane writes published)
        if (kc < 7) { loadW(WB0 + (uint32_t)(((kc+1)&1)*32768), gh, gl, kc+1, nRows, t); CP_COMMIT(); cp_wait<1>(); }
        else cp_wait<0>();
        __syncthreads();                       // tile kc visible
        uint32_t WB = WB0 + (uint32_t)((kc&1)*32768);

        // A fragments: af[ks][mi][4]; LD4 gives pairs {tt, tt+4, tt+8, tt+12}
        uint32_t af[2][2][4];
        #pragma unroll
        for (int mi = 0; mi < 2; mi++) {
            uint32_t ad = su + (uint32_t)((Ao + (mi*16 + g)*144 + kc*16 + tt*4)*4);
            uint32_t q0,q1,q2,q3,p0,p1,p2,p3;
            LD4(q0,q1,q2,q3, ad);
            LD4(p0,p1,p2,p3, ad + 8*144*4);
            af[0][mi][0]=q0; af[0][mi][2]=q1; af[1][mi][0]=q2; af[1][mi][2]=q3;
            af[0][mi][1]=p0; af[0][mi][3]=p1; af[1][mi][1]=p2; af[1][mi][3]=p3;
        }
        // B fragments
        uint32_t bh[2][NT][2], bl[2][NT][2];
        #pragma unroll
        for (int nt = 0; nt < NT; nt++) {
            uint32_t bd = WB + (uint32_t)((wn*NT + nt)*1024 + (g*4 + tt)*16);
            uint32_t q0,q1,q2,q3;
            LD4(q0,q1,q2,q3, bd);
            bh[0][nt][0]=q0; bh[0][nt][1]=q1; bh[1][nt][0]=q2; bh[1][nt][1]=q3;
            LD4(q0,q1,q2,q3, bd + 512);
            bl[0][nt][0]=q0; bl[0][nt][1]=q1; bl[1][nt][0]=q2; bl[1][nt][1]=q3;
        }
        #pragma unroll
        for (int ks = 0; ks < 2; ks++)
            #pragma unroll
            for (int mi = 0; mi < 2; mi++)
                #pragma unroll
                for (int nt = 0; nt < NT; nt++) {
                    mmaf16(ch[mi][nt], af[ks][mi], bh[ks][nt]);
                    mmaf16(cl[mi][nt], af[ks][mi], bl[ks][nt]);
                }
    }
    __syncthreads();
}

__global__ __launch_bounds__(256, 2)
void mlp_f16(const float* __restrict__ noisy, const float* __restrict__ target,
             const float* __restrict__ in_w,  const float* __restrict__ in_b,
             const float* __restrict__ ly_b1, const float* __restrict__ ly_g,
             const float* __restrict__ ly_be, const float* __restrict__ ly_b2,
             const float* __restrict__ out_b1, const float* __restrict__ out_w2,
             const float* __restrict__ out_b2, float* __restrict__ out)
{
    extern __shared__ float sm[];
    uint32_t su = smem_to_u32(sm);
    int t = threadIdx.x, lane = t & 31;
    int wn = t >> 5;                       // warp grid 1(M) x 8(N)
    int g = lane >> 2, tt = lane & 3;
    int b = blockIdx.x >> 8, row0 = (blockIdx.x & 255) << 5;

    float* feat = sm + O_FEAT;

    if (t < 32) {   // fused nn_reduce (32 rows)
        int pi = b*NN + row0 + t;
        float best = g_pbest[pi]; int bi = g_pidx[pi];
        #pragma unroll
        for (int s = 1; s < 4; s++) {
            float vv = g_pbest[s*(BB*NN) + pi];
            if (vv < best) { best = vv; bi = g_pidx[s*(BB*NN) + pi]; }
        }
        const float* tc = target + ((size_t)b*NN + bi)*3;
        feat[t*6+0] = noisy[(size_t)pi*3+0]; feat[t*6+1] = noisy[(size_t)pi*3+1]; feat[t*6+2] = noisy[(size_t)pi*3+2];
        feat[t*6+3] = tc[0]; feat[t*6+4] = tc[1]; feat[t*6+5] = tc[2];
    }
    // pre-issue W1 layer0 tile0
    loadW(su + (uint32_t)(O_WB*4), g_w1h, g_w1l, 0, 256, t); CP_COMMIT();
    __syncthreads();

    // ---- input build in fragment layout: residual xr in registers ----
    float xr[2][4][4];
    {
        const float* tp = g_tproj + b*256;
        float fr[2][2][6];
        #pragma unroll
        for (int mi = 0; mi < 2; mi++)
            #pragma unroll
            for (int h = 0; h < 2; h++) {
                int row = mi*16 + h*8 + g;
                #pragma unroll
                for (int k = 0; k < 6; k++) fr[mi][h][k] = feat[row*6 + k];
            }
        #pragma unroll
        for (int nt = 0; nt < 4; nt++) {
            int bc = wn*32 + nt*8 + 2*tt;
            #pragma unroll
            for (int half = 0; half < 2; half++) {
                int col = bc + half;
                float base = in_b[col] + tp[col];
                float w[6];
                #pragma unroll
                for (int k = 0; k < 6; k++) w[k] = in_w[k*256 + col];
                #pragma unroll
                for (int mi = 0; mi < 2; mi++)
                    #pragma unroll
                    for (int h = 0; h < 2; h++) {
                        float a = base;
                        #pragma unroll
                        for (int k = 0; k < 6; k++) a = fmaf(fr[mi][h][k], w[k], a);
                        xr[mi][nt][h*2 + half] = a;
                    }
            }
        }
        // store act plane: per (mi,h) one STS.128 at col u32 = wn*16 + tt*4 (+nt)
        #pragma unroll
        for (int mi = 0; mi < 2; mi++)
            #pragma unroll
            for (int h = 0; h < 2; h++) {
                int row = mi*16 + h*8 + g;
                uint32_t w4[4];
                #pragma unroll
                for (int nt = 0; nt < 4; nt++) w4[nt] = packh2(xr[mi][nt][h*2], xr[mi][nt][h*2+1]);
                ST4(su + (uint32_t)((O_XH + row*144 + wn*16 + tt*4)*4), w4[0], w4[1], w4[2], w4[3]);
            }
    }
    // gemm's first __syncthreads publishes plane writes

    // ---- 4 residual layers ----
    #pragma unroll 1
    for (int lay = 0; lay < 4; lay++) {
        const float* b1p = ly_b1 + lay*256;
        const float* gap = ly_g  + lay*256;
        const float* bep = ly_be + lay*256;
        const float* b2p = ly_b2 + lay*256;

        // GEMM1: D = x @ W1
        float ch[2][4][4], cl[2][4][4];
        #pragma unroll
        for (int mi = 0; mi < 2; mi++)
            #pragma unroll
            for (int nt = 0; nt < 4; nt++)
                #pragma unroll
                for (int e = 0; e < 4; e++) { ch[mi][nt][e] = 0.f; cl[mi][nt][e] = 0.f; }
        gemm_f16p<4>(su, O_XH, g_w1h + lay*32768, g_w1l + lay*32768, 256, ch, cl, t, wn, g, tt);

        // pre-issue GEMM2 tile0 (overlaps epilogue1)
        loadW(su + (uint32_t)(O_WB*4), g_w2h + lay*32768, g_w2l + lay*32768, 0, 256, t); CP_COMMIT();

        // epilogue1: combine into ch (v = ch + cl/2048 + b1), LN stats
        float S[2][2] = {{0,0},{0,0}}, Q[2][2] = {{0,0},{0,0}};
        #pragma unroll
        for (int mi = 0; mi < 2; mi++)
            #pragma unroll
            for (int nt = 0; nt < 4; nt++) {
                int bc = wn*32 + nt*8 + 2*tt;
                float b0 = b1p[bc], b1v = b1p[bc + 1];
                float v0 = fmaf(cl[mi][nt][0], INV2048, ch[mi][nt][0]) + b0;
                float v1 = fmaf(cl[mi][nt][1], INV2048, ch[mi][nt][1]) + b1v;
                float v2 = fmaf(cl[mi][nt][2], INV2048, ch[mi][nt][2]) + b0;
                float v3 = fmaf(cl[mi][nt][3], INV2048, ch[mi][nt][3]) + b1v;
                ch[mi][nt][0]=v0; ch[mi][nt][1]=v1; ch[mi][nt][2]=v2; ch[mi][nt][3]=v3;
                S[mi][0] += v0 + v1; Q[mi][0] = fmaf(v0,v0,fmaf(v1,v1,Q[mi][0]));
                S[mi][1] += v2 + v3; Q[mi][1] = fmaf(v2,v2,fmaf(v3,v3,Q[mi][1]));
            }
        #pragma unroll
        for (int mi = 0; mi < 2; mi++)
            #pragma unroll
            for (int h = 0; h < 2; h++) {
                float s = S[mi][h], q = Q[mi][h];
                s += __shfl_xor_sync(~0u, s, 1); s += __shfl_xor_sync(~0u, s, 2);
                q += __shfl_xor_sync(~0u, q, 1); q += __shfl_xor_sync(~0u, q, 2);
                if (tt == 0) {
                    int row = mi*16 + h*8 + g;
                    sm[O_SRS + row*8 + wn] = s;
                    sm[O_SRQ + row*8 + wn] = q;
                }
            }
        __syncthreads();
        if (t < 32) {
            float s = 0.f, q = 0.f;
            #pragma unroll
            for (int i = 0; i < 8; i++) { s += sm[O_SRS + t*8 + i]; q += sm[O_SRQ + t*8 + i]; }
            float mu = s * (1.f/256.f);
            sm[O_RS + t] = rsqrtf(fmaf(-mu, mu, q * (1.f/256.f)) + 1e-5f);
            sm[O_MU + t] = mu;
        }
        __syncthreads();
        // LN + SiLU -> h plane (STS.128 per (mi,h))
        #pragma unroll
        for (int mi = 0; mi < 2; mi++)
            #pragma unroll
            for (int h = 0; h < 2; h++) {
                int row = mi*16 + h*8 + g;
                float mu = sm[O_MU + row], rs = sm[O_RS + row];
                uint32_t w4[4];
                #pragma unroll
                for (int nt = 0; nt < 4; nt++) {
                    int bc = wn*32 + nt*8 + 2*tt;
                    float h0 = silu(fmaf((ch[mi][nt][2*h]   - mu)*rs, gap[bc],   bep[bc]));
                    float h1 = silu(fmaf((ch[mi][nt][2*h+1] - mu)*rs, gap[bc+1], bep[bc+1]));
                    w4[nt] = packh2(h0, h1);
                }
                ST4(su + (uint32_t)((O_HH + row*144 + wn*16 + tt*4)*4), w4[0], w4[1], w4[2], w4[3]);
            }

        // GEMM2: D = h @ W2 (tile0 pre-issued; first sync publishes h writes)
        #pragma unroll
        for (int mi = 0; mi < 2; mi++)
            #pragma unroll
            for (int nt = 0; nt < 4; nt++)
                #pragma unroll
                for (int e = 0; e < 4; e++) { ch[mi][nt][e] = 0.f; cl[mi][nt][e] = 0.f; }
        gemm_f16p<4>(su, O_HH, g_w2h + lay*32768, g_w2l + lay*32768, 256, ch, cl, t, wn, g, tt);

        // pre-issue next tile0 (next W1 or head) — overlaps epilogue2
        if (lay < 3) loadW(su + (uint32_t)(O_WB*4), g_w1h + (lay+1)*32768, g_w1l + (lay+1)*32768, 0, 256, t);
        else         loadW(su + (uint32_t)(O_WB*4), g_owh, g_owl, 0, 128, t);
        CP_COMMIT();

        // epilogue2: xr(regs) += D + b2; refresh act plane
        #pragma unroll
        for (int mi = 0; mi < 2; mi++)
            #pragma unroll
            for (int h = 0; h < 2; h++) {
                int row = mi*16 + h*8 + g;
                uint32_t w4[4];
                #pragma unroll
                for (int nt = 0; nt < 4; nt++) {
                    int bc = wn*32 + nt*8 + 2*tt;
                    float x0 = xr[mi][nt][2*h]   + fmaf(cl[mi][nt][2*h],   INV2048, ch[mi][nt][2*h])   + b2p[bc];
                    float x1 = xr[mi][nt][2*h+1] + fmaf(cl[mi][nt][2*h+1], INV2048, ch[mi][nt][2*h+1]) + b2p[bc + 1];
                    xr[mi][nt][2*h] = x0; xr[mi][nt][2*h+1] = x1;
                    w4[nt] = packh2(x0, x1);
                }
                ST4(su + (uint32_t)((O_XH + row*144 + wn*16 + tt*4)*4), w4[0], w4[1], w4[2], w4[3]);
            }
    }

    // ---- head GEMM: D = x @ out_w1 (N=128, tile0 pre-issued) ----
    {
        float ch[2][2][4], cl[2][2][4];
        #pragma unroll
        for (int mi = 0; mi < 2; mi++)
            #pragma unroll
            for (int nt = 0; nt < 2; nt++)
                #pragma unroll
                for (int e = 0; e < 4; e++) { ch[mi][nt][e] = 0.f; cl[mi][nt][e] = 0.f; }
        gemm_f16p<2>(su, O_XH, g_owh, g_owl, 128, ch, cl, t, wn, g, tt);

        // y1 = silu(D + b1) -> fp32 [32][132] in HH region
        float* y1f = sm + O_HH;
        #pragma unroll
        for (int mi = 0; mi < 2; mi++)
            #pragma unroll
            for (int h = 0; h < 2; h++) {
                int row = mi*16 + h*8 + g;
                #pragma unroll
                for (int nt = 0; nt < 2; nt++) {
                    int bc = wn*16 + nt*8 + 2*tt;
                    float v0 = fmaf(cl[mi][nt][2*h],   INV2048, ch[mi][nt][2*h])   + out_b1[bc];
                    float v1 = fmaf(cl[mi][nt][2*h+1], INV2048, ch[mi][nt][2*h+1]) + out_b1[bc+1];
                    y1f[row*132 + bc]     = silu(v0);
                    y1f[row*132 + bc + 1] = silu(v1);
                }
            }
    }
    __syncthreads();

    // ---- final: score = y1 @ out_w2 + out_b2 (128 -> 3, fp32) ----
    if (t < 96) {
        int rr = t / 3, p = t - rr*3;
        float a = out_b2[p];
        const float* y = sm + O_HH + rr*132;
        #pragma unroll 8
        for (int k = 0; k < 128; k++) a = fmaf(y[k], out_w2[k*3 + p], a);
        out[(size_t)((b*NN + row0 + rr)*3 + p)] = a;
    }
}

// =====================================================================
extern "C" void kernel_launch(void* const* d_in, const int* in_sizes, int n_in,
                              void* d_out, int out_size)
{
    const float* noisy  = (const float*)d_in[0];
    const float* target = (const float*)d_in[1];
    const int*   tsteps = (const int*)  d_in[2];
    const float* te_w1  = (const float*)d_in[3];
    const float* te_b1  = (const float*)d_in[4];
    const float* te_w2  = (const float*)d_in[5];
    const float* te_b2  = (const float*)d_in[6];
    const float* tp_w   = (const float*)d_in[7];
    const float* tp_b   = (const float*)d_in[8];
    const float* in_w   = (const float*)d_in[9];
    const float* in_b   = (const float*)d_in[10];
    const float* ly_w1  = (const float*)d_in[11];
    const float* ly_b1  = (const float*)d_in[12];
    const float* ly_g   = (const float*)d_in[13];
    const float* ly_be  = (const float*)d_in[14];
    const float* ly_w2  = (const float*)d_in[15];
    const float* ly_b2  = (const float*)d_in[16];
    const float* out_w1 = (const float*)d_in[17];
    const float* out_b1 = (const float*)d_in[18];
    const float* out_w2 = (const float*)d_in[19];
    const float* out_b2 = (const float*)d_in[20];
    float* out = (float*)d_out;

    cudaFuncSetAttribute(mlp_f16, cudaFuncAttributeMaxDynamicSharedMemorySize, SMEM_BYTES);

    splitw_kernel<<<576, 256>>>(ly_w1, ly_w2, out_w1);
    temb_kernel<<<4, 512>>>(tsteps, te_w1, te_b1, te_w2, te_b2, tp_w, tp_b);
    nn_kernel<<<1024, 128>>>(noisy, target);
    mlp_f16<<<1024, 256, SMEM_BYTES>>>(noisy, target, in_w, in_b,
                                       ly_b1, ly_g, ly_be, ly_b2,
                                       out_b1, out_w2, out_b2, out);
}

// round 13
// speedup vs baseline: 1.1342x; 1.0344x over previous
#include <cuda_runtime.h>
#include <cuda_fp16.h>
#include <math.h>
#include <cstdint>

#define BB 4
#define NN 8192

// ---------------- device scratch ----------------
__device__ float g_tproj[BB*256];
__device__ float g_pbest[4*BB*NN];
__device__ int   g_pidx [4*BB*NN];
// fp16 weight planes: [N][128] u32 (2 f16/u32 along K), k-pairs M-permuted within 16-groups
// hi = f16(W);  lo = f16((W - hi)*2048)
__device__ uint32_t g_w1h[4*256*128], g_w1l[4*256*128];
__device__ uint32_t g_w2h[4*256*128], g_w2l[4*256*128];
__device__ uint32_t g_owh[128*128],   g_owl[128*128];

// ================= helpers =================
__device__ __forceinline__ uint32_t smem_to_u32(const void* p) {
    uint32_t a;
    asm("{ .reg .u64 t; cvta.to.shared.u64 t, %1; cvt.u32.u64 %0, t; }" : "=r"(a) : "l"(p));
    return a;
}
#define LD4(r0,r1,r2,r3,ba) asm volatile("ld.shared.v4.u32 {%0,%1,%2,%3}, [%4];" \
    : "=r"(r0),"=r"(r1),"=r"(r2),"=r"(r3) : "r"(ba))
#define ST4(ba,r0,r1,r2,r3) asm volatile("st.shared.v4.b32 [%0], {%1,%2,%3,%4};" \
    :: "r"(ba),"r"(r0),"r"(r1),"r"(r2),"r"(r3) : "memory")

__device__ __forceinline__ uint32_t packh2(float x0, float x1) {
    uint32_t u;
    asm("cvt.rn.f16x2.f32 %0, %1, %2;" : "=r"(u) : "f"(x1), "f"(x0));
    return u;
}
// split two floats into f16 hi pair and f16 lo pair (lo scaled by 2048)
__device__ __forceinline__ void splitx2(float x0, float x1, uint32_t& hi, uint32_t& lo) {
    hi = packh2(x0, x1);
    __half2 hh = *reinterpret_cast<__half2*>(&hi);
    float h0 = __low2float(hh), h1 = __high2float(hh);
    lo = packh2((x0 - h0)*2048.f, (x1 - h1)*2048.f);
}
__device__ __forceinline__ void mmaf16(float c[4], const uint32_t a[4], const uint32_t b[2]) {
    asm volatile(
        "mma.sync.aligned.m16n8k16.row.col.f32.f16.f16.f32 "
        "{%0,%1,%2,%3}, {%4,%5,%6,%7}, {%8,%9}, {%0,%1,%2,%3};"
        : "+f"(c[0]), "+f"(c[1]), "+f"(c[2]), "+f"(c[3])
        : "r"(a[0]), "r"(a[1]), "r"(a[2]), "r"(a[3]), "r"(b[0]), "r"(b[1]));
}
__device__ __forceinline__ float silu(float x) { return x / (1.0f + __expf(-x)); }
#define INV2048 4.8828125e-4f

// smem u32 offsets; per-CTA total ~59KB -> 2 CTAs/SM (reg-bound)
// planes: 32 rows x 144 u32 (row stride 576B = 64 mod 128 -> LDS.128 conflict-free)
#define O_XH    0        // 4608  residual hi (f16x2)
#define O_XL    4608     // 4608  residual lo (f16x2, x2048)
#define O_HH    9216     // 4608  h plane; reused as fp32 y1 [32][132]
#define O_SRS   13824    // 32 x 8 f
#define O_SRQ   14080
#define O_MU    14336
#define O_RS    14368
#define O_FEAT  14400    // 32 x 6 f
#define SMEM_U32 14592
#define SMEM_BYTES (SMEM_U32*4)

// ============ weight transpose + exact fp16 hi/lo split + M-perm ============
__global__ void splitw_kernel(const float* __restrict__ ly_w1,
                              const float* __restrict__ ly_w2,
                              const float* __restrict__ out_w1)
{
    __shared__ float ts[32][33];
    int m = blockIdx.x >> 6, tile = blockIdx.x & 63;
    const float* src; uint32_t *dh, *dl; int N = 256;
    if (m < 4)      { src = ly_w1 + m*65536;     dh = g_w1h + m*32768; dl = g_w1l + m*32768; }
    else if (m < 8) { src = ly_w2 + (m-4)*65536; dh = g_w2h + (m-4)*32768; dl = g_w2l + (m-4)*32768; }
    else            { src = out_w1;              dh = g_owh; dl = g_owl; N = 128; }
    int tn = (tile & 7) * 32, tk = (tile >> 3) * 32;   // one 32-k tile = one 16-pair group
    if (tn >= N) return;
    int lx = threadIdx.x & 31, ly = threadIdx.x >> 5;
    #pragma unroll
    for (int i = 0; i < 32; i += 8) ts[ly+i][lx] = src[(tk+ly+i)*N + tn + lx];
    __syncthreads();
    int kk = lx & 15; bool ishi = lx < 16;
    int pos = ((kk & 3) << 2) | (kk >> 2);             // M-perm: transpose within 16
    #pragma unroll
    for (int i = 0; i < 32; i += 8) {
        int nl = ly + i;
        float x0 = ts[2*kk][nl], x1 = ts[2*kk+1][nl];
        __half2 hh = __floats2half2_rn(x0, x1);
        float h0 = __low2float(hh), h1 = __high2float(hh);
        __half2 llv = __floats2half2_rn((x0 - h0)*2048.f, (x1 - h1)*2048.f);
        int idx = (tn + nl)*128 + (tk >> 1) + pos;
        if (ishi) dh[idx] = *reinterpret_cast<uint32_t*>(&hh);
        else      dl[idx] = *reinterpret_cast<uint32_t*>(&llv);
    }
}

// ============ time embedding ============
__global__ void temb_kernel(const int* __restrict__ timesteps,
                            const float* __restrict__ te_w1, const float* __restrict__ te_b1,
                            const float* __restrict__ te_w2, const float* __restrict__ te_b2,
                            const float* __restrict__ tp_w,  const float* __restrict__ tp_b)
{
    __shared__ float emb[128], h1[512], h2[512];
    int b = blockIdx.x, t = threadIdx.x;
    if (t < 64) {
        float fr = expf((float)t * (-logf(10000.0f) / 63.0f));
        float an = (float)timesteps[b] * fr;
        emb[t] = sinf(an); emb[t+64] = cosf(an);
    }
    __syncthreads();
    { float a = te_b1[t];
      #pragma unroll 4
      for (int k = 0; k < 128; k++) a = fmaf(emb[k], te_w1[k*512+t], a);
      h1[t] = a / (1.0f + expf(-a)); }
    __syncthreads();
    { float a = te_b2[t];
      #pragma unroll 4
      for (int k = 0; k < 512; k++) a = fmaf(h1[k], te_w2[k*512+t], a);
      h2[t] = a; }
    __syncthreads();
    if (t < 256) {
        float a = tp_b[t];
        #pragma unroll 4
        for (int k = 0; k < 512; k++) a = fmaf(h2[k], tp_w[k*256+t], a);
        g_tproj[b*256+t] = a;
    }
}

// ============ nearest neighbor ============
#define TSZ 2048
__global__ void nn_kernel(const float* __restrict__ noisy, const float* __restrict__ target)
{
    __shared__ float4 ts[TSZ];
    int b = blockIdx.x >> 8, chunk = (blockIdx.x >> 2) & 63, slice = blockIdx.x & 3;
    int t = threadIdx.x;
    const float4* tg4 = (const float4*)(target + ((size_t)b*NN + (size_t)slice*TSZ) * 3);
    for (int p4 = t; p4 < TSZ/4; p4 += 128) {
        float4 v0 = tg4[3*p4], v1 = tg4[3*p4+1], v2 = tg4[3*p4+2];
        ts[4*p4+0] = make_float4(v0.x, v0.y, v0.z, 0.5f*(v0.x*v0.x + v0.y*v0.y + v0.z*v0.z));
        ts[4*p4+1] = make_float4(v0.w, v1.x, v1.y, 0.5f*(v0.w*v0.w + v1.x*v1.x + v1.y*v1.y));
        ts[4*p4+2] = make_float4(v1.z, v1.w, v2.x, 0.5f*(v1.z*v1.z + v1.w*v1.w + v2.x*v2.x));
        ts[4*p4+3] = make_float4(v2.y, v2.z, v2.w, 0.5f*(v2.y*v2.y + v2.z*v2.z + v2.w*v2.w));
    }
    __syncthreads();
    int p = chunk*128 + t;
    const float* q = noisy + ((size_t)b*NN + p) * 3;
    float qx = -q[0], qy = -q[1], qz = -q[2];
    float best0 = INFINITY, best1 = INFINITY; int b0 = 0, b1 = 1;
    #pragma unroll 4
    for (int j = 0; j < TSZ; j += 2) {
        float4 v0 = ts[j], v1 = ts[j+1];
        float e0 = fmaf(qx, v0.x, v0.w); e0 = fmaf(qy, v0.y, e0); e0 = fmaf(qz, v0.z, e0);
        float e1 = fmaf(qx, v1.x, v1.w); e1 = fmaf(qy, v1.y, e1); e1 = fmaf(qz, v1.z, e1);
        if (e0 < best0) { best0 = e0; b0 = j; }
        if (e1 < best1) { best1 = e1; b1 = j+1; }
    }
    float best = best0; int bidx = b0;
    if (best1 < best0) { best = best1; bidx = b1; }
    int pi = b*NN + p;
    g_pbest[slice*(BB*NN) + pi] = best;
    g_pidx [slice*(BB*NN) + pi] = slice*TSZ + bidx;
}

// ============ fused fp16 weight-pair MLP, B direct from gmem (no k-loop barriers) ============
// NT n8-tiles/warp: 4 => N=256 (8 n-warps), 2 => N=128
template<int NT>
__device__ __forceinline__ void gemm_ldg(uint32_t su, int Ao,
                                         const uint32_t* __restrict__ gh,
                                         const uint32_t* __restrict__ gl,
                                         float ch[2][NT][4], float cl[2][NT][4],
                                         int wn, int g, int tt)
{
    // per-nt weight row pointers (fragment-exact layout in gmem)
    const uint32_t* ph[NT];
    const uint32_t* pl[NT];
    #pragma unroll
    for (int nt = 0; nt < NT; nt++) {
        int n = wn*(NT*8) + nt*8 + g;
        ph[nt] = gh + n*128 + tt*4;
        pl[nt] = gl + n*128 + tt*4;
    }
    #pragma unroll
    for (int kc = 0; kc < 8; kc++) {
        // B fragments straight from L2
        uint4 bhv[NT], blv[NT];
        #pragma unroll
        for (int nt = 0; nt < NT; nt++) {
            bhv[nt] = *(const uint4*)(ph[nt] + kc*16);
            blv[nt] = *(const uint4*)(pl[nt] + kc*16);
        }
        // A fragments from smem plane
        uint32_t af[2][2][4];
        #pragma unroll
        for (int mi = 0; mi < 2; mi++) {
            uint32_t ad = su + (uint32_t)((Ao + (mi*16 + g)*144 + kc*16 + tt*4)*4);
            uint32_t q0,q1,q2,q3,p0,p1,p2,p3;
            LD4(q0,q1,q2,q3, ad);
            LD4(p0,p1,p2,p3, ad + 8*144*4);
            af[0][mi][0]=q0; af[0][mi][2]=q1; af[1][mi][0]=q2; af[1][mi][2]=q3;
            af[0][mi][1]=p0; af[0][mi][3]=p1; af[1][mi][1]=p2; af[1][mi][3]=p3;
        }
        #pragma unroll
        for (int ks = 0; ks < 2; ks++)
            #pragma unroll
            for (int mi = 0; mi < 2; mi++)
                #pragma unroll
                for (int nt = 0; nt < NT; nt++) {
                    uint32_t bh[2] = { ks ? bhv[nt].z : bhv[nt].x, ks ? bhv[nt].w : bhv[nt].y };
                    uint32_t bl[2] = { ks ? blv[nt].z : blv[nt].x, ks ? blv[nt].w : blv[nt].y };
                    mmaf16(ch[mi][nt], af[ks][mi], bh);
                    mmaf16(cl[mi][nt], af[ks][mi], bl);
                }
    }
}

__global__ __launch_bounds__(256, 2)
void mlp_f16(const float* __restrict__ noisy, const float* __restrict__ target,
             const float* __restrict__ in_w,  const float* __restrict__ in_b,
             const float* __restrict__ ly_b1, const float* __restrict__ ly_g,
             const float* __restrict__ ly_be, const float* __restrict__ ly_b2,
             const float* __restrict__ out_b1, const float* __restrict__ out_w2,
             const float* __restrict__ out_b2, float* __restrict__ out)
{
    extern __shared__ float sm[];
    uint32_t su = smem_to_u32(sm);
    int t = threadIdx.x, lane = t & 31;
    int wn = t >> 5;                       // warp grid 1(M) x 8(N)
    int g = lane >> 2, tt = lane & 3;
    int b = blockIdx.x >> 8, row0 = (blockIdx.x & 255) << 5;

    float* feat = sm + O_FEAT;

    if (t < 32) {   // fused nn_reduce (32 rows)
        int pi = b*NN + row0 + t;
        float best = g_pbest[pi]; int bi = g_pidx[pi];
        #pragma unroll
        for (int s = 1; s < 4; s++) {
            float vv = g_pbest[s*(BB*NN) + pi];
            if (vv < best) { best = vv; bi = g_pidx[s*(BB*NN) + pi]; }
        }
        const float* tc = target + ((size_t)b*NN + bi)*3;
        feat[t*6+0] = noisy[(size_t)pi*3+0]; feat[t*6+1] = noisy[(size_t)pi*3+1]; feat[t*6+2] = noisy[(size_t)pi*3+2];
        feat[t*6+3] = tc[0]; feat[t*6+4] = tc[1]; feat[t*6+5] = tc[2];
    }
    __syncthreads();

    // ---- input build in fragment layout -> XH/XL residual planes ----
    {
        const float* tp = g_tproj + b*256;
        float fr[2][2][6];
        #pragma unroll
        for (int mi = 0; mi < 2; mi++)
            #pragma unroll
            for (int h = 0; h < 2; h++) {
                int row = mi*16 + h*8 + g;
                #pragma unroll
                for (int k = 0; k < 6; k++) fr[mi][h][k] = feat[row*6 + k];
            }
        uint32_t wh[2][2][4], wl[2][2][4];   // [mi][h][nt]
        #pragma unroll
        for (int nt = 0; nt < 4; nt++) {
            int bc = wn*32 + nt*8 + 2*tt;
            float xv[2][2][2];
            #pragma unroll
            for (int half = 0; half < 2; half++) {
                int col = bc + half;
                float base = in_b[col] + tp[col];
                float w[6];
                #pragma unroll
                for (int k = 0; k < 6; k++) w[k] = in_w[k*256 + col];
                #pragma unroll
                for (int mi = 0; mi < 2; mi++)
                    #pragma unroll
                    for (int h = 0; h < 2; h++) {
                        float a = base;
                        #pragma unroll
                        for (int k = 0; k < 6; k++) a = fmaf(fr[mi][h][k], w[k], a);
                        xv[mi][h][half] = a;
                    }
            }
            #pragma unroll
            for (int mi = 0; mi < 2; mi++)
                #pragma unroll
                for (int h = 0; h < 2; h++)
                    splitx2(xv[mi][h][0], xv[mi][h][1], wh[mi][h][nt], wl[mi][h][nt]);
        }
        #pragma unroll
        for (int mi = 0; mi < 2; mi++)
            #pragma unroll
            for (int h = 0; h < 2; h++) {
                int row = mi*16 + h*8 + g;
                uint32_t off = (uint32_t)((row*144 + wn*16 + tt*4)*4);
                ST4(su + (uint32_t)(O_XH*4) + off, wh[mi][h][0], wh[mi][h][1], wh[mi][h][2], wh[mi][h][3]);
                ST4(su + (uint32_t)(O_XL*4) + off, wl[mi][h][0], wl[mi][h][1], wl[mi][h][2], wl[mi][h][3]);
            }
    }
    __syncthreads();   // publish XH/XL

    // ---- 4 residual layers ----
    #pragma unroll 1
    for (int lay = 0; lay < 4; lay++) {
        const float* b1p = ly_b1 + lay*256;
        const float* gap = ly_g  + lay*256;
        const float* bep = ly_be + lay*256;
        const float* b2p = ly_b2 + lay*256;

        // GEMM1: D = x @ W1 (no barriers inside)
        float ch[2][4][4], cl[2][4][4];
        #pragma unroll
        for (int mi = 0; mi < 2; mi++)
            #pragma unroll
            for (int nt = 0; nt < 4; nt++)
                #pragma unroll
                for (int e = 0; e < 4; e++) { ch[mi][nt][e] = 0.f; cl[mi][nt][e] = 0.f; }
        gemm_ldg<4>(su, O_XH, g_w1h + lay*32768, g_w1l + lay*32768, ch, cl, wn, g, tt);

        // epilogue1: combine into ch (v = ch + cl/2048 + b1), LN stats
        float S[2][2] = {{0,0},{0,0}}, Q[2][2] = {{0,0},{0,0}};
        #pragma unroll
        for (int mi = 0; mi < 2; mi++)
            #pragma unroll
            for (int nt = 0; nt < 4; nt++) {
                int bc = wn*32 + nt*8 + 2*tt;
                float b0 = b1p[bc], b1v = b1p[bc + 1];
                float v0 = fmaf(cl[mi][nt][0], INV2048, ch[mi][nt][0]) + b0;
                float v1 = fmaf(cl[mi][nt][1], INV2048, ch[mi][nt][1]) + b1v;
                float v2 = fmaf(cl[mi][nt][2], INV2048, ch[mi][nt][2]) + b0;
                float v3 = fmaf(cl[mi][nt][3], INV2048, ch[mi][nt][3]) + b1v;
                ch[mi][nt][0]=v0; ch[mi][nt][1]=v1; ch[mi][nt][2]=v2; ch[mi][nt][3]=v3;
                S[mi][0] += v0 + v1; Q[mi][0] = fmaf(v0,v0,fmaf(v1,v1,Q[mi][0]));
                S[mi][1] += v2 + v3; Q[mi][1] = fmaf(v2,v2,fmaf(v3,v3,Q[mi][1]));
            }
        #pragma unroll
        for (int mi = 0; mi < 2; mi++)
            #pragma unroll
            for (int h = 0; h < 2; h++) {
                float s = S[mi][h], q = Q[mi][h];
                s += __shfl_xor_sync(~0u, s, 1); s += __shfl_xor_sync(~0u, s, 2);
                q += __shfl_xor_sync(~0u, q, 1); q += __shfl_xor_sync(~0u, q, 2);
                if (tt == 0) {
                    int row = mi*16 + h*8 + g;
                    sm[O_SRS + row*8 + wn] = s;
                    sm[O_SRQ + row*8 + wn] = q;
                }
            }
        __syncthreads();
        if (t < 32) {
            float s = 0.f, q = 0.f;
            #pragma unroll
            for (int i = 0; i < 8; i++) { s += sm[O_SRS + t*8 + i]; q += sm[O_SRQ + t*8 + i]; }
            float mu = s * (1.f/256.f);
            sm[O_RS + t] = rsqrtf(fmaf(-mu, mu, q * (1.f/256.f)) + 1e-5f);
            sm[O_MU + t] = mu;
        }
        __syncthreads();
        // LN + SiLU -> h plane (STS.128 per (mi,h))
        #pragma unroll
        for (int mi = 0; mi < 2; mi++)
            #pragma unroll
            for (int h = 0; h < 2; h++) {
                int row = mi*16 + h*8 + g;
                float mu = sm[O_MU + row], rs = sm[O_RS + row];
                uint32_t w4[4];
                #pragma unroll
                for (int nt = 0; nt < 4; nt++) {
                    int bc = wn*32 + nt*8 + 2*tt;
                    float h0 = silu(fmaf((ch[mi][nt][2*h]   - mu)*rs, gap[bc],   bep[bc]));
                    float h1 = silu(fmaf((ch[mi][nt][2*h+1] - mu)*rs, gap[bc+1], bep[bc+1]));
                    w4[nt] = packh2(h0, h1);
                }
                ST4(su + (uint32_t)((O_HH + row*144 + wn*16 + tt*4)*4), w4[0], w4[1], w4[2], w4[3]);
            }
        __syncthreads();   // publish h plane

        // GEMM2: D = h @ W2
        #pragma unroll
        for (int mi = 0; mi < 2; mi++)
            #pragma unroll
            for (int nt = 0; nt < 4; nt++)
                #pragma unroll
                for (int e = 0; e < 4; e++) { ch[mi][nt][e] = 0.f; cl[mi][nt][e] = 0.f; }
        gemm_ldg<4>(su, O_HH, g_w2h + lay*32768, g_w2l + lay*32768, ch, cl, wn, g, tt);

        // epilogue2: x = x_old(XH/XL planes) + D + b2; refresh planes
        #pragma unroll
        for (int mi = 0; mi < 2; mi++)
            #pragma unroll
            for (int h = 0; h < 2; h++) {
                int row = mi*16 + h*8 + g;
                uint32_t off = (uint32_t)((row*144 + wn*16 + tt*4)*4);
                uint32_t oh0,oh1,oh2,oh3, ol0,ol1,ol2,ol3;
                LD4(oh0,oh1,oh2,oh3, su + (uint32_t)(O_XH*4) + off);
                LD4(ol0,ol1,ol2,ol3, su + (uint32_t)(O_XL*4) + off);
                uint32_t ohs[4] = {oh0,oh1,oh2,oh3};
                uint32_t ols[4] = {ol0,ol1,ol2,ol3};
                uint32_t nh[4], nl[4];
                #pragma unroll
                for (int nt = 0; nt < 4; nt++) {
                    int bc = wn*32 + nt*8 + 2*tt;
                    float2 xo = __half22float2(*reinterpret_cast<__half2*>(&ohs[nt]));
                    float2 xl = __half22float2(*reinterpret_cast<__half2*>(&ols[nt]));
                    float x0 = fmaf(xl.x, INV2048, xo.x) + fmaf(cl[mi][nt][2*h],   INV2048, ch[mi][nt][2*h])   + b2p[bc];
                    float x1 = fmaf(xl.y, INV2048, xo.y) + fmaf(cl[mi][nt][2*h+1], INV2048, ch[mi][nt][2*h+1]) + b2p[bc + 1];
                    splitx2(x0, x1, nh[nt], nl[nt]);
                }
                ST4(su + (uint32_t)(O_XH*4) + off, nh[0], nh[1], nh[2], nh[3]);
                ST4(su + (uint32_t)(O_XL*4) + off, nl[0], nl[1], nl[2], nl[3]);
            }
        __syncthreads();   // publish refreshed x planes
    }

    // ---- head GEMM: D = x @ out_w1 (N=128) ----
    {
        float ch[2][2][4], cl[2][2][4];
        #pragma unroll
        for (int mi = 0; mi < 2; mi++)
            #pragma unroll
            for (int nt = 0; nt < 2; nt++)
                #pragma unroll
                for (int e = 0; e < 4; e++) { ch[mi][nt][e] = 0.f; cl[mi][nt][e] = 0.f; }
        gemm_ldg<2>(su, O_XH, g_owh, g_owl, ch, cl, wn, g, tt);

        __syncthreads();   // XH reads done before HH region reused as fp32 y1
        float* y1f = sm + O_HH;
        #pragma unroll
        for (int mi = 0; mi < 2; mi++)
            #pragma unroll
            for (int h = 0; h < 2; h++) {
                int row = mi*16 + h*8 + g;
                #pragma unroll
                for (int nt = 0; nt < 2; nt++) {
                    int bc = wn*16 + nt*8 + 2*tt;
                    float v0 = fmaf(cl[mi][nt][2*h],   INV2048, ch[mi][nt][2*h])   + out_b1[bc];
                    float v1 = fmaf(cl[mi][nt][2*h+1], INV2048, ch[mi][nt][2*h+1]) + out_b1[bc+1];
                    y1f[row*132 + bc]     = silu(v0);
                    y1f[row*132 + bc + 1] = silu(v1);
                }
            }
    }
    __syncthreads();

    // ---- final: score = y1 @ out_w2 + out_b2 (128 -> 3, fp32) ----
    if (t < 96) {
        int rr = t / 3, p = t - rr*3;
        float a = out_b2[p];
        const float* y = sm + O_HH + rr*132;
        #pragma unroll 8
        for (int k = 0; k < 128; k++) a = fmaf(y[k], out_w2[k*3 + p], a);
        out[(size_t)((b*NN + row0 + rr)*3 + p)] = a;
    }
}

// =====================================================================
extern "C" void kernel_launch(void* const* d_in, const int* in_sizes, int n_in,
                              void* d_out, int out_size)
{
    const float* noisy  = (const float*)d_in[0];
    const float* target = (const float*)d_in[1];
    const int*   tsteps = (const int*)  d_in[2];
    const float* te_w1  = (const float*)d_in[3];
    const float* te_b1  = (const float*)d_in[4];
    const float* te_w2  = (const float*)d_in[5];
    const float* te_b2  = (const float*)d_in[6];
    const float* tp_w   = (const float*)d_in[7];
    const float* tp_b   = (const float*)d_in[8];
    const float* in_w   = (const float*)d_in[9];
    const float* in_b   = (const float*)d_in[10];
    const float* ly_w1  = (const float*)d_in[11];
    const float* ly_b1  = (const float*)d_in[12];
    const float* ly_g   = (const float*)d_in[13];
    const float* ly_be  = (const float*)d_in[14];
    const float* ly_w2  = (const float*)d_in[15];
    const float* ly_b2  = (const float*)d_in[16];
    const float* out_w1 = (const float*)d_in[17];
    const float* out_b1 = (const float*)d_in[18];
    const float* out_w2 = (const float*)d_in[19];
    const float* out_b2 = (const float*)d_in[20];
    float* out = (float*)d_out;

    cudaFuncSetAttribute(mlp_f16, cudaFuncAttributeMaxDynamicSharedMemorySize, SMEM_BYTES);

    splitw_kernel<<<576, 256>>>(ly_w1, ly_w2, out_w1);
    temb_kernel<<<4, 512>>>(tsteps, te_w1, te_b1, te_w2, te_b2, tp_w, tp_b);
    nn_kernel<<<1024, 128>>>(noisy, target);
    mlp_f16<<<1024, 256, SMEM_BYTES>>>(noisy, target, in_w, in_b,
                                       ly_b1, ly_g, ly_be, ly_b2,
                                       out_b1, out_w2, out_b2, out);
}

// round 14
// speedup vs baseline: 1.1958x; 1.0542x over previous
#include <cuda_runtime.h>
#include <cuda_fp16.h>
#include <math.h>
#include <cstdint>

#define BB 4
#define NN 8192

// ---------------- device scratch ----------------
__device__ float g_tproj[BB*256];
__device__ float g_pbest[4*BB*NN];
__device__ int   g_pidx [4*BB*NN];
// fp16 weight planes: [N][128] u32 (2 f16/u32 along K), k-pairs M-permuted within 16-groups
// hi = f16(W);  lo = f16((W - hi)*2048)
__device__ uint32_t g_w1h[4*256*128], g_w1l[4*256*128];
__device__ uint32_t g_w2h[4*256*128], g_w2l[4*256*128];
__device__ uint32_t g_owh[128*128],   g_owl[128*128];

// ================= helpers =================
__device__ __forceinline__ uint32_t smem_to_u32(const void* p) {
    uint32_t a;
    asm("{ .reg .u64 t; cvta.to.shared.u64 t, %1; cvt.u32.u64 %0, t; }" : "=r"(a) : "l"(p));
    return a;
}
#define LD4(r0,r1,r2,r3,ba) asm volatile("ld.shared.v4.u32 {%0,%1,%2,%3}, [%4];" \
    : "=r"(r0),"=r"(r1),"=r"(r2),"=r"(r3) : "r"(ba))
#define ST4(ba,r0,r1,r2,r3) asm volatile("st.shared.v4.b32 [%0], {%1,%2,%3,%4};" \
    :: "r"(ba),"r"(r0),"r"(r1),"r"(r2),"r"(r3) : "memory")

__device__ __forceinline__ uint32_t packh2(float x0, float x1) {
    uint32_t u;
    asm("cvt.rn.f16x2.f32 %0, %1, %2;" : "=r"(u) : "f"(x1), "f"(x0));
    return u;
}
// split two floats into f16 hi pair and f16 lo pair (lo scaled by 2048)
__device__ __forceinline__ void splitx2(float x0, float x1, uint32_t& hi, uint32_t& lo) {
    hi = packh2(x0, x1);
    __half2 hh = *reinterpret_cast<__half2*>(&hi);
    float h0 = __low2float(hh), h1 = __high2float(hh);
    lo = packh2((x0 - h0)*2048.f, (x1 - h1)*2048.f);
}
__device__ __forceinline__ void mmaf16(float c[4], const uint32_t a[4], const uint32_t b[2]) {
    asm volatile(
        "mma.sync.aligned.m16n8k16.row.col.f32.f16.f16.f32 "
        "{%0,%1,%2,%3}, {%4,%5,%6,%7}, {%8,%9}, {%0,%1,%2,%3};"
        : "+f"(c[0]), "+f"(c[1]), "+f"(c[2]), "+f"(c[3])
        : "r"(a[0]), "r"(a[1]), "r"(a[2]), "r"(a[3]), "r"(b[0]), "r"(b[1]));
}
__device__ __forceinline__ float silu(float x) { return x / (1.0f + __expf(-x)); }
#define INV2048 4.8828125e-4f

// mlp smem u32 offsets; planes: 32 rows x 144 u32 (stride 576B = 64 mod 128, LDS.128 conflict-free)
#define O_XH    0        // 4608  residual hi (f16x2)
#define O_XL    4608     // 4608  residual lo (f16x2, x2048)
#define O_HH    9216     // 4608  h plane; reused as fp32 y1 [32][132]
#define O_SRS   13824    // 32 x 8 f
#define O_SRQ   14080
#define O_MU    14336
#define O_RS    14368
#define O_FEAT  14400    // 32 x 6 f
#define SMEM_U32 14592
#define SMEM_BYTES (SMEM_U32*4)

// =====================================================================
// prep_kernel: fuses nn / splitw / temb (independent) into one launch.
// blocks [0,512): nn    — 256 thr, 2 point-chunks share one target-slice staging
// blocks [512,1088): splitw
// blocks [1088,1092): temb (256-thr variant)
// =====================================================================
#define TSZ 2048
#define PREP_NN    512
#define PREP_SPW   1088
#define PREP_TOTAL 1092

__global__ __launch_bounds__(256)
void prep_kernel(const float* __restrict__ noisy, const float* __restrict__ target,
                 const int* __restrict__ timesteps,
                 const float* __restrict__ te_w1, const float* __restrict__ te_b1,
                 const float* __restrict__ te_w2, const float* __restrict__ te_b2,
                 const float* __restrict__ tp_w,  const float* __restrict__ tp_b,
                 const float* __restrict__ ly_w1, const float* __restrict__ ly_w2,
                 const float* __restrict__ out_w1)
{
    __shared__ float4 shm4[TSZ];     // 32 KB, aliased by all roles
    int t = threadIdx.x;
    int blk = blockIdx.x;

    if (blk < PREP_NN) {
        // ---------------- nn role ----------------
        int b = blk >> 7, cp = (blk >> 2) & 31, slice = blk & 3;
        const float4* tg4 = (const float4*)(target + ((size_t)b*NN + (size_t)slice*TSZ) * 3);
        for (int p4 = t; p4 < TSZ/4; p4 += 256) {
            float4 v0 = tg4[3*p4], v1 = tg4[3*p4+1], v2 = tg4[3*p4+2];
            shm4[4*p4+0] = make_float4(v0.x, v0.y, v0.z, 0.5f*(v0.x*v0.x + v0.y*v0.y + v0.z*v0.z));
            shm4[4*p4+1] = make_float4(v0.w, v1.x, v1.y, 0.5f*(v0.w*v0.w + v1.x*v1.x + v1.y*v1.y));
            shm4[4*p4+2] = make_float4(v1.z, v1.w, v2.x, 0.5f*(v1.z*v1.z + v1.w*v1.w + v2.x*v2.x));
            shm4[4*p4+3] = make_float4(v2.y, v2.z, v2.w, 0.5f*(v2.y*v2.y + v2.z*v2.z + v2.w*v2.w));
        }
        __syncthreads();
        int p = cp*256 + t;
        const float* q = noisy + ((size_t)b*NN + p) * 3;
        float qx = -q[0], qy = -q[1], qz = -q[2];
        float best0 = INFINITY, best1 = INFINITY; int b0 = 0, b1 = 1;
        #pragma unroll 4
        for (int j = 0; j < TSZ; j += 2) {
            float4 v0 = shm4[j], v1 = shm4[j+1];
            float e0 = fmaf(qx, v0.x, v0.w); e0 = fmaf(qy, v0.y, e0); e0 = fmaf(qz, v0.z, e0);
            float e1 = fmaf(qx, v1.x, v1.w); e1 = fmaf(qy, v1.y, e1); e1 = fmaf(qz, v1.z, e1);
            if (e0 < best0) { best0 = e0; b0 = j; }
            if (e1 < best1) { best1 = e1; b1 = j+1; }
        }
        float best = best0; int bidx = b0;
        if (best1 < best0) { best = best1; bidx = b1; }
        int pi = b*NN + p;
        g_pbest[slice*(BB*NN) + pi] = best;
        g_pidx [slice*(BB*NN) + pi] = slice*TSZ + bidx;
    } else if (blk < PREP_SPW) {
        // ---------------- splitw role ----------------
        float (*ts)[33] = reinterpret_cast<float(*)[33]>(shm4);
        int sb = blk - PREP_NN;
        int m = sb >> 6, tile = sb & 63;
        const float* src; uint32_t *dh, *dl; int N = 256;
        if (m < 4)      { src = ly_w1 + m*65536;     dh = g_w1h + m*32768; dl = g_w1l + m*32768; }
        else if (m < 8) { src = ly_w2 + (m-4)*65536; dh = g_w2h + (m-4)*32768; dl = g_w2l + (m-4)*32768; }
        else            { src = out_w1;              dh = g_owh; dl = g_owl; N = 128; }
        int tn = (tile & 7) * 32, tk = (tile >> 3) * 32;
        if (tn >= N) return;
        int lx = t & 31, ly = t >> 5;
        #pragma unroll
        for (int i = 0; i < 32; i += 8) ts[ly+i][lx] = src[(tk+ly+i)*N + tn + lx];
        __syncthreads();
        int kk = lx & 15; bool ishi = lx < 16;
        int pos = ((kk & 3) << 2) | (kk >> 2);   // M-perm: transpose within 16
        #pragma unroll
        for (int i = 0; i < 32; i += 8) {
            int nl = ly + i;
            float x0 = ts[2*kk][nl], x1 = ts[2*kk+1][nl];
            __half2 hh = __floats2half2_rn(x0, x1);
            float h0 = __low2float(hh), h1 = __high2float(hh);
            __half2 llv = __floats2half2_rn((x0 - h0)*2048.f, (x1 - h1)*2048.f);
            int idx = (tn + nl)*128 + (tk >> 1) + pos;
            if (ishi) dh[idx] = *reinterpret_cast<uint32_t*>(&hh);
            else      dl[idx] = *reinterpret_cast<uint32_t*>(&llv);
        }
    } else {
        // ---------------- temb role (256 threads) ----------------
        float* sp  = (float*)shm4;
        float* emb = sp;           // 128
        float* h1  = sp + 128;     // 512
        float* h2  = sp + 640;     // 512
        int b = blk - PREP_SPW;
        if (t < 64) {
            float fr = expf((float)t * (-logf(10000.0f) / 63.0f));
            float an = (float)timesteps[b] * fr;
            emb[t] = sinf(an); emb[t+64] = cosf(an);
        }
        __syncthreads();
        #pragma unroll
        for (int j = t; j < 512; j += 256) {
            float a = te_b1[j];
            #pragma unroll 4
            for (int k = 0; k < 128; k++) a = fmaf(emb[k], te_w1[k*512+j], a);
            h1[j] = a / (1.0f + expf(-a));
        }
        __syncthreads();
        #pragma unroll
        for (int j = t; j < 512; j += 256) {
            float a = te_b2[j];
            #pragma unroll 4
            for (int k = 0; k < 512; k++) a = fmaf(h1[k], te_w2[k*512+j], a);
            h2[j] = a;
        }
        __syncthreads();
        {
            float a = tp_b[t];
            #pragma unroll 4
            for (int k = 0; k < 512; k++) a = fmaf(h2[k], tp_w[k*256+t], a);
            g_tproj[b*256+t] = a;
        }
    }
}

// ============ fused fp16 weight-pair MLP, B direct from gmem (no k-loop barriers) ============
// NT n8-tiles/warp: 4 => N=256 (8 n-warps), 2 => N=128
template<int NT>
__device__ __forceinline__ void gemm_ldg(uint32_t su, int Ao,
                                         const uint32_t* __restrict__ gh,
                                         const uint32_t* __restrict__ gl,
                                         float ch[2][NT][4], float cl[2][NT][4],
                                         int wn, int g, int tt)
{
    const uint32_t* ph[NT];
    const uint32_t* pl[NT];
    #pragma unroll
    for (int nt = 0; nt < NT; nt++) {
        int n = wn*(NT*8) + nt*8 + g;
        ph[nt] = gh + n*128 + tt*4;
        pl[nt] = gl + n*128 + tt*4;
    }
    #pragma unroll
    for (int kc = 0; kc < 8; kc++) {
        uint4 bhv[NT], blv[NT];
        #pragma unroll
        for (int nt = 0; nt < NT; nt++) {
            bhv[nt] = *(const uint4*)(ph[nt] + kc*16);
            blv[nt] = *(const uint4*)(pl[nt] + kc*16);
        }
        uint32_t af[2][2][4];
        #pragma unroll
        for (int mi = 0; mi < 2; mi++) {
            uint32_t ad = su + (uint32_t)((Ao + (mi*16 + g)*144 + kc*16 + tt*4)*4);
            uint32_t q0,q1,q2,q3,p0,p1,p2,p3;
            LD4(q0,q1,q2,q3, ad);
            LD4(p0,p1,p2,p3, ad + 8*144*4);
            af[0][mi][0]=q0; af[0][mi][2]=q1; af[1][mi][0]=q2; af[1][mi][2]=q3;
            af[0][mi][1]=p0; af[0][mi][3]=p1; af[1][mi][1]=p2; af[1][mi][3]=p3;
        }
        #pragma unroll
        for (int ks = 0; ks < 2; ks++)
            #pragma unroll
            for (int mi = 0; mi < 2; mi++)
                #pragma unroll
                for (int nt = 0; nt < NT; nt++) {
                    uint32_t bh[2] = { ks ? bhv[nt].z : bhv[nt].x, ks ? bhv[nt].w : bhv[nt].y };
                    uint32_t bl[2] = { ks ? blv[nt].z : blv[nt].x, ks ? blv[nt].w : blv[nt].y };
                    mmaf16(ch[mi][nt], af[ks][mi], bh);
                    mmaf16(cl[mi][nt], af[ks][mi], bl);
                }
    }
}

__global__ __launch_bounds__(256, 2)
void mlp_f16(const float* __restrict__ noisy, const float* __restrict__ target,
             const float* __restrict__ in_w,  const float* __restrict__ in_b,
             const float* __restrict__ ly_b1, const float* __restrict__ ly_g,
             const float* __restrict__ ly_be, const float* __restrict__ ly_b2,
             const float* __restrict__ out_b1, const float* __restrict__ out_w2,
             const float* __restrict__ out_b2, float* __restrict__ out)
{
    extern __shared__ float sm[];
    uint32_t su = smem_to_u32(sm);
    int t = threadIdx.x, lane = t & 31;
    int wn = t >> 5;                       // warp grid 1(M) x 8(N)
    int g = lane >> 2, tt = lane & 3;
    int b = blockIdx.x >> 8, row0 = (blockIdx.x & 255) << 5;

    float* feat = sm + O_FEAT;

    if (t < 32) {   // fused nn_reduce (32 rows)
        int pi = b*NN + row0 + t;
        float best = g_pbest[pi]; int bi = g_pidx[pi];
        #pragma unroll
        for (int s = 1; s < 4; s++) {
            float vv = g_pbest[s*(BB*NN) + pi];
            if (vv < best) { best = vv; bi = g_pidx[s*(BB*NN) + pi]; }
        }
        const float* tc = target + ((size_t)b*NN + bi)*3;
        feat[t*6+0] = noisy[(size_t)pi*3+0]; feat[t*6+1] = noisy[(size_t)pi*3+1]; feat[t*6+2] = noisy[(size_t)pi*3+2];
        feat[t*6+3] = tc[0]; feat[t*6+4] = tc[1]; feat[t*6+5] = tc[2];
    }
    __syncthreads();

    // ---- input build in fragment layout -> XH/XL residual planes ----
    {
        const float* tp = g_tproj + b*256;
        float fr[2][2][6];
        #pragma unroll
        for (int mi = 0; mi < 2; mi++)
            #pragma unroll
            for (int h = 0; h < 2; h++) {
                int row = mi*16 + h*8 + g;
                #pragma unroll
                for (int k = 0; k < 6; k++) fr[mi][h][k] = feat[row*6 + k];
            }
        uint32_t wh[2][2][4], wl[2][2][4];
        #pragma unroll
        for (int nt = 0; nt < 4; nt++) {
            int bc = wn*32 + nt*8 + 2*tt;
            float xv[2][2][2];
            #pragma unroll
            for (int half = 0; half < 2; half++) {
                int col = bc + half;
                float base = in_b[col] + tp[col];
                float w[6];
                #pragma unroll
                for (int k = 0; k < 6; k++) w[k] = in_w[k*256 + col];
                #pragma unroll
                for (int mi = 0; mi < 2; mi++)
                    #pragma unroll
                    for (int h = 0; h < 2; h++) {
                        float a = base;
                        #pragma unroll
                        for (int k = 0; k < 6; k++) a = fmaf(fr[mi][h][k], w[k], a);
                        xv[mi][h][half] = a;
                    }
            }
            #pragma unroll
            for (int mi = 0; mi < 2; mi++)
                #pragma unroll
                for (int h = 0; h < 2; h++)
                    splitx2(xv[mi][h][0], xv[mi][h][1], wh[mi][h][nt], wl[mi][h][nt]);
        }
        #pragma unroll
        for (int mi = 0; mi < 2; mi++)
            #pragma unroll
            for (int h = 0; h < 2; h++) {
                int row = mi*16 + h*8 + g;
                uint32_t off = (uint32_t)((row*144 + wn*16 + tt*4)*4);
                ST4(su + (uint32_t)(O_XH*4) + off, wh[mi][h][0], wh[mi][h][1], wh[mi][h][2], wh[mi][h][3]);
                ST4(su + (uint32_t)(O_XL*4) + off, wl[mi][h][0], wl[mi][h][1], wl[mi][h][2], wl[mi][h][3]);
            }
    }
    __syncthreads();   // publish XH/XL

    // ---- 4 residual layers ----
    #pragma unroll 1
    for (int lay = 0; lay < 4; lay++) {
        const float* b1p = ly_b1 + lay*256;
        const float* gap = ly_g  + lay*256;
        const float* bep = ly_be + lay*256;
        const float* b2p = ly_b2 + lay*256;

        // GEMM1: D = x @ W1 (no barriers inside)
        float ch[2][4][4], cl[2][4][4];
        #pragma unroll
        for (int mi = 0; mi < 2; mi++)
            #pragma unroll
            for (int nt = 0; nt < 4; nt++)
                #pragma unroll
                for (int e = 0; e < 4; e++) { ch[mi][nt][e] = 0.f; cl[mi][nt][e] = 0.f; }
        gemm_ldg<4>(su, O_XH, g_w1h + lay*32768, g_w1l + lay*32768, ch, cl, wn, g, tt);

        // epilogue1: combine into ch, LN stats
        float S[2][2] = {{0,0},{0,0}}, Q[2][2] = {{0,0},{0,0}};
        #pragma unroll
        for (int mi = 0; mi < 2; mi++)
            #pragma unroll
            for (int nt = 0; nt < 4; nt++) {
                int bc = wn*32 + nt*8 + 2*tt;
                float b0 = b1p[bc], b1v = b1p[bc + 1];
                float v0 = fmaf(cl[mi][nt][0], INV2048, ch[mi][nt][0]) + b0;
                float v1 = fmaf(cl[mi][nt][1], INV2048, ch[mi][nt][1]) + b1v;
                float v2 = fmaf(cl[mi][nt][2], INV2048, ch[mi][nt][2]) + b0;
                float v3 = fmaf(cl[mi][nt][3], INV2048, ch[mi][nt][3]) + b1v;
                ch[mi][nt][0]=v0; ch[mi][nt][1]=v1; ch[mi][nt][2]=v2; ch[mi][nt][3]=v3;
                S[mi][0] += v0 + v1; Q[mi][0] = fmaf(v0,v0,fmaf(v1,v1,Q[mi][0]));
                S[mi][1] += v2 + v3; Q[mi][1] = fmaf(v2,v2,fmaf(v3,v3,Q[mi][1]));
            }
        #pragma unroll
        for (int mi = 0; mi < 2; mi++)
            #pragma unroll
            for (int h = 0; h < 2; h++) {
                float s = S[mi][h], q = Q[mi][h];
                s += __shfl_xor_sync(~0u, s, 1); s += __shfl_xor_sync(~0u, s, 2);
                q += __shfl_xor_sync(~0u, q, 1); q += __shfl_xor_sync(~0u, q, 2);
                if (tt == 0) {
                    int row = mi*16 + h*8 + g;
                    sm[O_SRS + row*8 + wn] = s;
                    sm[O_SRQ + row*8 + wn] = q;
                }
            }
        __syncthreads();
        if (t < 32) {
            float s = 0.f, q = 0.f;
            #pragma unroll
            for (int i = 0; i < 8; i++) { s += sm[O_SRS + t*8 + i]; q += sm[O_SRQ + t*8 + i]; }
            float mu = s * (1.f/256.f);
            sm[O_RS + t] = rsqrtf(fmaf(-mu, mu, q * (1.f/256.f)) + 1e-5f);
            sm[O_MU + t] = mu;
        }
        __syncthreads();
        // LN + SiLU -> h plane
        #pragma unroll
        for (int mi = 0; mi < 2; mi++)
            #pragma unroll
            for (int h = 0; h < 2; h++) {
                int row = mi*16 + h*8 + g;
                float mu = sm[O_MU + row], rs = sm[O_RS + row];
                uint32_t w4[4];
                #pragma unroll
                for (int nt = 0; nt < 4; nt++) {
                    int bc = wn*32 + nt*8 + 2*tt;
                    float h0 = silu(fmaf((ch[mi][nt][2*h]   - mu)*rs, gap[bc],   bep[bc]));
                    float h1 = silu(fmaf((ch[mi][nt][2*h+1] - mu)*rs, gap[bc+1], bep[bc+1]));
                    w4[nt] = packh2(h0, h1);
                }
                ST4(su + (uint32_t)((O_HH + row*144 + wn*16 + tt*4)*4), w4[0], w4[1], w4[2], w4[3]);
            }
        __syncthreads();   // publish h plane

        // GEMM2: D = h @ W2
        #pragma unroll
        for (int mi = 0; mi < 2; mi++)
            #pragma unroll
            for (int nt = 0; nt < 4; nt++)
                #pragma unroll
                for (int e = 0; e < 4; e++) { ch[mi][nt][e] = 0.f; cl[mi][nt][e] = 0.f; }
        gemm_ldg<4>(su, O_HH, g_w2h + lay*32768, g_w2l + lay*32768, ch, cl, wn, g, tt);

        // epilogue2: x = x_old(XH/XL planes) + D + b2; refresh planes
        #pragma unroll
        for (int mi = 0; mi < 2; mi++)
            #pragma unroll
            for (int h = 0; h < 2; h++) {
                int row = mi*16 + h*8 + g;
                uint32_t off = (uint32_t)((row*144 + wn*16 + tt*4)*4);
                uint32_t oh0,oh1,oh2,oh3, ol0,ol1,ol2,ol3;
                LD4(oh0,oh1,oh2,oh3, su + (uint32_t)(O_XH*4) + off);
                LD4(ol0,ol1,ol2,ol3, su + (uint32_t)(O_XL*4) + off);
                uint32_t ohs[4] = {oh0,oh1,oh2,oh3};
                uint32_t ols[4] = {ol0,ol1,ol2,ol3};
                uint32_t nh[4], nl[4];
                #pragma unroll
                for (int nt = 0; nt < 4; nt++) {
                    int bc = wn*32 + nt*8 + 2*tt;
                    float2 xo = __half22float2(*reinterpret_cast<__half2*>(&ohs[nt]));
                    float2 xl = __half22float2(*reinterpret_cast<__half2*>(&ols[nt]));
                    float x0 = fmaf(xl.x, INV2048, xo.x) + fmaf(cl[mi][nt][2*h],   INV2048, ch[mi][nt][2*h])   + b2p[bc];
                    float x1 = fmaf(xl.y, INV2048, xo.y) + fmaf(cl[mi][nt][2*h+1], INV2048, ch[mi][nt][2*h+1]) + b2p[bc + 1];
                    splitx2(x0, x1, nh[nt], nl[nt]);
                }
                ST4(su + (uint32_t)(O_XH*4) + off, nh[0], nh[1], nh[2], nh[3]);
                ST4(su + (uint32_t)(O_XL*4) + off, nl[0], nl[1], nl[2], nl[3]);
            }
        __syncthreads();   // publish refreshed x planes
    }

    // ---- head GEMM: D = x @ out_w1 (N=128) ----
    {
        float ch[2][2][4], cl[2][2][4];
        #pragma unroll
        for (int mi = 0; mi < 2; mi++)
            #pragma unroll
            for (int nt = 0; nt < 2; nt++)
                #pragma unroll
                for (int e = 0; e < 4; e++) { ch[mi][nt][e] = 0.f; cl[mi][nt][e] = 0.f; }
        gemm_ldg<2>(su, O_XH, g_owh, g_owl, ch, cl, wn, g, tt);

        __syncthreads();   // XH reads done before HH region reused as fp32 y1
        float* y1f = sm + O_HH;
        #pragma unroll
        for (int mi = 0; mi < 2; mi++)
            #pragma unroll
            for (int h = 0; h < 2; h++) {
                int row = mi*16 + h*8 + g;
                #pragma unroll
                for (int nt = 0; nt < 2; nt++) {
                    int bc = wn*16 + nt*8 + 2*tt;
                    float v0 = fmaf(cl[mi][nt][2*h],   INV2048, ch[mi][nt][2*h])   + out_b1[bc];
                    float v1 = fmaf(cl[mi][nt][2*h+1], INV2048, ch[mi][nt][2*h+1]) + out_b1[bc+1];
                    y1f[row*132 + bc]     = silu(v0);
                    y1f[row*132 + bc + 1] = silu(v1);
                }
            }
    }
    __syncthreads();

    // ---- final: score = y1 @ out_w2 + out_b2 (128 -> 3, fp32) ----
    if (t < 96) {
        int rr = t / 3, p = t - rr*3;
        float a = out_b2[p];
        const float* y = sm + O_HH + rr*132;
        #pragma unroll 8
        for (int k = 0; k < 128; k++) a = fmaf(y[k], out_w2[k*3 + p], a);
        out[(size_t)((b*NN + row0 + rr)*3 + p)] = a;
    }
}

// =====================================================================
extern "C" void kernel_launch(void* const* d_in, const int* in_sizes, int n_in,
                              void* d_out, int out_size)
{
    const float* noisy  = (const float*)d_in[0];
    const float* target = (const float*)d_in[1];
    const int*   tsteps = (const int*)  d_in[2];
    const float* te_w1  = (const float*)d_in[3];
    const float* te_b1  = (const float*)d_in[4];
    const float* te_w2  = (const float*)d_in[5];
    const float* te_b2  = (const float*)d_in[6];
    const float* tp_w   = (const float*)d_in[7];
    const float* tp_b   = (const float*)d_in[8];
    const float* in_w   = (const float*)d_in[9];
    const float* in_b   = (const float*)d_in[10];
    const float* ly_w1  = (const float*)d_in[11];
    const float* ly_b1  = (const float*)d_in[12];
    const float* ly_g   = (const float*)d_in[13];
    const float* ly_be  = (const float*)d_in[14];
    const float* ly_w2  = (const float*)d_in[15];
    const float* ly_b2  = (const float*)d_in[16];
    const float* out_w1 = (const float*)d_in[17];
    const float* out_b1 = (const float*)d_in[18];
    const float* out_w2 = (const float*)d_in[19];
    const float* out_b2 = (const float*)d_in[20];
    float* out = (float*)d_out;

    cudaFuncSetAttribute(mlp_f16, cudaFuncAttributeMaxDynamicSharedMemorySize, SMEM_BYTES);

    prep_kernel<<<PREP_TOTAL, 256>>>(noisy, target, tsteps,
                                     te_w1, te_b1, te_w2, te_b2, tp_w, tp_b,
                                     ly_w1, ly_w2, out_w1);
    mlp_f16<<<1024, 256, SMEM_BYTES>>>(noisy, target, in_w, in_b,
                                       ly_b1, ly_g, ly_be, ly_b2,
                                       out_b1, out_w2, out_b2, out);
}

// round 15
// speedup vs baseline: 1.8211x; 1.5229x over previous
#include <cuda_runtime.h>
#include <cuda_fp16.h>
#include <math.h>
#include <cstdint>

#define BB 4
#define NN 8192
#define NSL 8

// ---------------- device scratch ----------------
__device__ float g_tproj[BB*256];
__device__ float g_pbest[NSL*BB*NN];
__device__ int   g_pidx [NSL*BB*NN];
// fp16 weight planes: [N][128] u32 (2 f16/u32 along K), k-pairs M-permuted within 16-groups
// hi = f16(W);  lo = f16((W - hi)*2048)
__device__ uint32_t g_w1h[4*256*128], g_w1l[4*256*128];
__device__ uint32_t g_w2h[4*256*128], g_w2l[4*256*128];
__device__ uint32_t g_owh[128*128],   g_owl[128*128];

// ================= helpers =================
__device__ __forceinline__ uint32_t smem_to_u32(const void* p) {
    uint32_t a;
    asm("{ .reg .u64 t; cvta.to.shared.u64 t, %1; cvt.u32.u64 %0, t; }" : "=r"(a) : "l"(p));
    return a;
}
#define LD4(r0,r1,r2,r3,ba) asm volatile("ld.shared.v4.u32 {%0,%1,%2,%3}, [%4];" \
    : "=r"(r0),"=r"(r1),"=r"(r2),"=r"(r3) : "r"(ba))
#define ST4(ba,r0,r1,r2,r3) asm volatile("st.shared.v4.b32 [%0], {%1,%2,%3,%4};" \
    :: "r"(ba),"r"(r0),"r"(r1),"r"(r2),"r"(r3) : "memory")

__device__ __forceinline__ uint32_t packh2(float x0, float x1) {
    uint32_t u;
    asm("cvt.rn.f16x2.f32 %0, %1, %2;" : "=r"(u) : "f"(x1), "f"(x0));
    return u;
}
__device__ __forceinline__ void splitx2(float x0, float x1, uint32_t& hi, uint32_t& lo) {
    hi = packh2(x0, x1);
    __half2 hh = *reinterpret_cast<__half2*>(&hi);
    float h0 = __low2float(hh), h1 = __high2float(hh);
    lo = packh2((x0 - h0)*2048.f, (x1 - h1)*2048.f);
}
__device__ __forceinline__ void mmaf16(float c[4], const uint32_t a[4], const uint32_t b[2]) {
    asm volatile(
        "mma.sync.aligned.m16n8k16.row.col.f32.f16.f16.f32 "
        "{%0,%1,%2,%3}, {%4,%5,%6,%7}, {%8,%9}, {%0,%1,%2,%3};"
        : "+f"(c[0]), "+f"(c[1]), "+f"(c[2]), "+f"(c[3])
        : "r"(a[0]), "r"(a[1]), "r"(a[2]), "r"(a[3]), "r"(b[0]), "r"(b[1]));
}
__device__ __forceinline__ float silu(float x) { return x / (1.0f + __expf(-x)); }
#define INV2048 4.8828125e-4f

// mlp smem u32 offsets; planes: 32 rows x 144 u32 (stride 576B = 64 mod 128, LDS.128 conflict-free)
#define O_XH    0        // 4608  residual hi (f16x2)
#define O_XL    4608     // 4608  residual lo (f16x2, x2048)
#define O_HH    9216     // 4608  h plane; reused as fp32 y1 [32][132]
#define O_SRS   13824    // 32 x 8 f
#define O_SRQ   14080
#define O_MU    14336
#define O_RS    14368
#define O_FEAT  14400    // 32 x 6 f
#define SMEM_U32 14592
#define SMEM_BYTES (SMEM_U32*4)

// =====================================================================
// prep_kernel: fuses nn / splitw / temb (independent) into one launch.
// blocks [0,256): nn — 8 slices of 1024 targets; 256 thr, 4 points/thread
// blocks [256,832): splitw
// blocks [832,836): temb
// =====================================================================
#define SLTS 1024
#define PREP_NN    256
#define PREP_SPW   832
#define PREP_TOTAL 836

__global__ __launch_bounds__(256)
void prep_kernel(const float* __restrict__ noisy, const float* __restrict__ target,
                 const int* __restrict__ timesteps,
                 const float* __restrict__ te_w1, const float* __restrict__ te_b1,
                 const float* __restrict__ te_w2, const float* __restrict__ te_b2,
                 const float* __restrict__ tp_w,  const float* __restrict__ tp_b,
                 const float* __restrict__ ly_w1, const float* __restrict__ ly_w2,
                 const float* __restrict__ out_w1)
{
    __shared__ float4 shm4[SLTS];     // 16 KB, aliased by all roles
    int t = threadIdx.x;
    int blk = blockIdx.x;

    if (blk < PREP_NN) {
        // ---------------- nn role: Q=4 points/thread over 1024-target slice ----------------
        int b = blk >> 6, pg = (blk >> 3) & 7, slice = blk & 7;
        // stage slice: 1024 targets = 768 float4; thread t stages 3 float4 (targets 4t..4t+3)
        const float4* tg4 = (const float4*)(target + ((size_t)b*NN + (size_t)slice*SLTS) * 3);
        {
            float4 v0 = tg4[3*t], v1 = tg4[3*t+1], v2 = tg4[3*t+2];
            shm4[4*t+0] = make_float4(v0.x, v0.y, v0.z, 0.5f*(v0.x*v0.x + v0.y*v0.y + v0.z*v0.z));
            shm4[4*t+1] = make_float4(v0.w, v1.x, v1.y, 0.5f*(v0.w*v0.w + v1.x*v1.x + v1.y*v1.y));
            shm4[4*t+2] = make_float4(v1.z, v1.w, v2.x, 0.5f*(v1.z*v1.z + v1.w*v1.w + v2.x*v2.x));
            shm4[4*t+3] = make_float4(v2.y, v2.z, v2.w, 0.5f*(v2.y*v2.y + v2.z*v2.z + v2.w*v2.w));
        }
        __syncthreads();
        // 4 query points: p_i = pg*1024 + t + 256*i
        float qx[4], qy[4], qz[4], best[4];
        int bidx[4];
        int p0 = pg*1024 + t;
        #pragma unroll
        for (int i = 0; i < 4; i++) {
            const float* q = noisy + ((size_t)b*NN + p0 + 256*i) * 3;
            qx[i] = -q[0]; qy[i] = -q[1]; qz[i] = -q[2];
            best[i] = INFINITY; bidx[i] = 0;
        }
        #pragma unroll 2
        for (int j = 0; j < SLTS; j++) {
            float4 v = shm4[j];
            #pragma unroll
            for (int i = 0; i < 4; i++) {
                float e = fmaf(qx[i], v.x, v.w);
                e = fmaf(qy[i], v.y, e);
                e = fmaf(qz[i], v.z, e);
                if (e < best[i]) { best[i] = e; bidx[i] = j; }
            }
        }
        #pragma unroll
        for (int i = 0; i < 4; i++) {
            int pi = b*NN + p0 + 256*i;
            g_pbest[slice*(BB*NN) + pi] = best[i];
            g_pidx [slice*(BB*NN) + pi] = slice*SLTS + bidx[i];
        }
    } else if (blk < PREP_SPW) {
        // ---------------- splitw role ----------------
        float (*ts)[33] = reinterpret_cast<float(*)[33]>(shm4);
        int sb = blk - PREP_NN;
        int m = sb >> 6, tile = sb & 63;
        const float* src; uint32_t *dh, *dl; int N = 256;
        if (m < 4)      { src = ly_w1 + m*65536;     dh = g_w1h + m*32768; dl = g_w1l + m*32768; }
        else if (m < 8) { src = ly_w2 + (m-4)*65536; dh = g_w2h + (m-4)*32768; dl = g_w2l + (m-4)*32768; }
        else            { src = out_w1;              dh = g_owh; dl = g_owl; N = 128; }
        int tn = (tile & 7) * 32, tk = (tile >> 3) * 32;
        if (tn >= N) return;
        int lx = t & 31, ly = t >> 5;
        #pragma unroll
        for (int i = 0; i < 32; i += 8) ts[ly+i][lx] = src[(tk+ly+i)*N + tn + lx];
        __syncthreads();
        int kk = lx & 15; bool ishi = lx < 16;
        int pos = ((kk & 3) << 2) | (kk >> 2);   // M-perm: transpose within 16
        #pragma unroll
        for (int i = 0; i < 32; i += 8) {
            int nl = ly + i;
            float x0 = ts[2*kk][nl], x1 = ts[2*kk+1][nl];
            __half2 hh = __floats2half2_rn(x0, x1);
            float h0 = __low2float(hh), h1 = __high2float(hh);
            __half2 llv = __floats2half2_rn((x0 - h0)*2048.f, (x1 - h1)*2048.f);
            int idx = (tn + nl)*128 + (tk >> 1) + pos;
            if (ishi) dh[idx] = *reinterpret_cast<uint32_t*>(&hh);
            else      dl[idx] = *reinterpret_cast<uint32_t*>(&llv);
        }
    } else {
        // ---------------- temb role (256 threads) ----------------
        float* sp  = (float*)shm4;
        float* emb = sp;           // 128
        float* h1  = sp + 128;     // 512
        float* h2  = sp + 640;     // 512
        int b = blk - PREP_SPW;
        if (t < 64) {
            float fr = expf((float)t * (-logf(10000.0f) / 63.0f));
            float an = (float)timesteps[b] * fr;
            emb[t] = sinf(an); emb[t+64] = cosf(an);
        }
        __syncthreads();
        #pragma unroll
        for (int j = t; j < 512; j += 256) {
            float a = te_b1[j];
            #pragma unroll 4
            for (int k = 0; k < 128; k++) a = fmaf(emb[k], te_w1[k*512+j], a);
            h1[j] = a / (1.0f + expf(-a));
        }
        __syncthreads();
        #pragma unroll
        for (int j = t; j < 512; j += 256) {
            float a = te_b2[j];
            #pragma unroll 4
            for (int k = 0; k < 512; k++) a = fmaf(h1[k], te_w2[k*512+j], a);
            h2[j] = a;
        }
        __syncthreads();
        {
            float a = tp_b[t];
            #pragma unroll 4
            for (int k = 0; k < 512; k++) a = fmaf(h2[k], tp_w[k*256+t], a);
            g_tproj[b*256+t] = a;
        }
    }
}

// ============ fused fp16 weight-pair MLP, B direct from gmem (no k-loop barriers) ============
template<int NT>
__device__ __forceinline__ void gemm_ldg(uint32_t su, int Ao,
                                         const uint32_t* __restrict__ gh,
                                         const uint32_t* __restrict__ gl,
                                         float ch[2][NT][4], float cl[2][NT][4],
                                         int wn, int g, int tt)
{
    const uint32_t* ph[NT];
    const uint32_t* pl[NT];
    #pragma unroll
    for (int nt = 0; nt < NT; nt++) {
        int n = wn*(NT*8) + nt*8 + g;
        ph[nt] = gh + n*128 + tt*4;
        pl[nt] = gl + n*128 + tt*4;
    }
    #pragma unroll
    for (int kc = 0; kc < 8; kc++) {
        uint4 bhv[NT], blv[NT];
        #pragma unroll
        for (int nt = 0; nt < NT; nt++) {
            bhv[nt] = *(const uint4*)(ph[nt] + kc*16);
            blv[nt] = *(const uint4*)(pl[nt] + kc*16);
        }
        uint32_t af[2][2][4];
        #pragma unroll
        for (int mi = 0; mi < 2; mi++) {
            uint32_t ad = su + (uint32_t)((Ao + (mi*16 + g)*144 + kc*16 + tt*4)*4);
            uint32_t q0,q1,q2,q3,p0,p1,p2,p3;
            LD4(q0,q1,q2,q3, ad);
            LD4(p0,p1,p2,p3, ad + 8*144*4);
            af[0][mi][0]=q0; af[0][mi][2]=q1; af[1][mi][0]=q2; af[1][mi][2]=q3;
            af[0][mi][1]=p0; af[0][mi][3]=p1; af[1][mi][1]=p2; af[1][mi][3]=p3;
        }
        #pragma unroll
        for (int ks = 0; ks < 2; ks++)
            #pragma unroll
            for (int mi = 0; mi < 2; mi++)
                #pragma unroll
                for (int nt = 0; nt < NT; nt++) {
                    uint32_t bh[2] = { ks ? bhv[nt].z : bhv[nt].x, ks ? bhv[nt].w : bhv[nt].y };
                    uint32_t bl[2] = { ks ? blv[nt].z : blv[nt].x, ks ? blv[nt].w : blv[nt].y };
                    mmaf16(ch[mi][nt], af[ks][mi], bh);
                    mmaf16(cl[mi][nt], af[ks][mi], bl);
                }
    }
}

__global__ __launch_bounds__(256, 2)
void mlp_f16(const float* __restrict__ noisy, const float* __restrict__ target,
             const float* __restrict__ in_w,  const float* __restrict__ in_b,
             const float* __restrict__ ly_b1, const float* __restrict__ ly_g,
             const float* __restrict__ ly_be, const float* __restrict__ ly_b2,
             const float* __restrict__ out_b1, const float* __restrict__ out_w2,
             const float* __restrict__ out_b2, float* __restrict__ out)
{
    extern __shared__ float sm[];
    uint32_t su = smem_to_u32(sm);
    int t = threadIdx.x, lane = t & 31;
    int wn = t >> 5;                       // warp grid 1(M) x 8(N)
    int g = lane >> 2, tt = lane & 3;
    int b = blockIdx.x >> 8, row0 = (blockIdx.x & 255) << 5;

    float* feat = sm + O_FEAT;

    if (t < 32) {   // fused nn_reduce over 8 slices (ascending => first-min)
        int pi = b*NN + row0 + t;
        float best = g_pbest[pi]; int bi = g_pidx[pi];
        #pragma unroll
        for (int s = 1; s < NSL; s++) {
            float vv = g_pbest[s*(BB*NN) + pi];
            if (vv < best) { best = vv; bi = g_pidx[s*(BB*NN) + pi]; }
        }
        const float* tc = target + ((size_t)b*NN + bi)*3;
        feat[t*6+0] = noisy[(size_t)pi*3+0]; feat[t*6+1] = noisy[(size_t)pi*3+1]; feat[t*6+2] = noisy[(size_t)pi*3+2];
        feat[t*6+3] = tc[0]; feat[t*6+4] = tc[1]; feat[t*6+5] = tc[2];
    }
    __syncthreads();

    // ---- input build in fragment layout -> XH/XL residual planes ----
    {
        const float* tp = g_tproj + b*256;
        float fr[2][2][6];
        #pragma unroll
        for (int mi = 0; mi < 2; mi++)
            #pragma unroll
            for (int h = 0; h < 2; h++) {
                int row = mi*16 + h*8 + g;
                #pragma unroll
                for (int k = 0; k < 6; k++) fr[mi][h][k] = feat[row*6 + k];
            }
        uint32_t wh[2][2][4], wl[2][2][4];
        #pragma unroll
        for (int nt = 0; nt < 4; nt++) {
            int bc = wn*32 + nt*8 + 2*tt;
            float xv[2][2][2];
            #pragma unroll
            for (int half = 0; half < 2; half++) {
                int col = bc + half;
                float base = in_b[col] + tp[col];
                float w[6];
                #pragma unroll
                for (int k = 0; k < 6; k++) w[k] = in_w[k*256 + col];
                #pragma unroll
                for (int mi = 0; mi < 2; mi++)
                    #pragma unroll
                    for (int h = 0; h < 2; h++) {
                        float a = base;
                        #pragma unroll
                        for (int k = 0; k < 6; k++) a = fmaf(fr[mi][h][k], w[k], a);
                        xv[mi][h][half] = a;
                    }
            }
            #pragma unroll
            for (int mi = 0; mi < 2; mi++)
                #pragma unroll
                for (int h = 0; h < 2; h++)
                    splitx2(xv[mi][h][0], xv[mi][h][1], wh[mi][h][nt], wl[mi][h][nt]);
        }
        #pragma unroll
        for (int mi = 0; mi < 2; mi++)
            #pragma unroll
            for (int h = 0; h < 2; h++) {
                int row = mi*16 + h*8 + g;
                uint32_t off = (uint32_t)((row*144 + wn*16 + tt*4)*4);
                ST4(su + (uint32_t)(O_XH*4) + off, wh[mi][h][0], wh[mi][h][1], wh[mi][h][2], wh[mi][h][3]);
                ST4(su + (uint32_t)(O_XL*4) + off, wl[mi][h][0], wl[mi][h][1], wl[mi][h][2], wl[mi][h][3]);
            }
    }
    __syncthreads();   // publish XH/XL

    // ---- 4 residual layers ----
    #pragma unroll 1
    for (int lay = 0; lay < 4; lay++) {
        const float* b1p = ly_b1 + lay*256;
        const float* gap = ly_g  + lay*256;
        const float* bep = ly_be + lay*256;
        const float* b2p = ly_b2 + lay*256;

        // GEMM1: D = x @ W1 (no barriers inside)
        float ch[2][4][4], cl[2][4][4];
        #pragma unroll
        for (int mi = 0; mi < 2; mi++)
            #pragma unroll
            for (int nt = 0; nt < 4; nt++)
                #pragma unroll
                for (int e = 0; e < 4; e++) { ch[mi][nt][e] = 0.f; cl[mi][nt][e] = 0.f; }
        gemm_ldg<4>(su, O_XH, g_w1h + lay*32768, g_w1l + lay*32768, ch, cl, wn, g, tt);

        // epilogue1: combine into ch, LN stats
        float S[2][2] = {{0,0},{0,0}}, Q[2][2] = {{0,0},{0,0}};
        #pragma unroll
        for (int mi = 0; mi < 2; mi++)
            #pragma unroll
            for (int nt = 0; nt < 4; nt++) {
                int bc = wn*32 + nt*8 + 2*tt;
                float b0 = b1p[bc], b1v = b1p[bc + 1];
                float v0 = fmaf(cl[mi][nt][0], INV2048, ch[mi][nt][0]) + b0;
                float v1 = fmaf(cl[mi][nt][1], INV2048, ch[mi][nt][1]) + b1v;
                float v2 = fmaf(cl[mi][nt][2], INV2048, ch[mi][nt][2]) + b0;
                float v3 = fmaf(cl[mi][nt][3], INV2048, ch[mi][nt][3]) + b1v;
                ch[mi][nt][0]=v0; ch[mi][nt][1]=v1; ch[mi][nt][2]=v2; ch[mi][nt][3]=v3;
                S[mi][0] += v0 + v1; Q[mi][0] = fmaf(v0,v0,fmaf(v1,v1,Q[mi][0]));
                S[mi][1] += v2 + v3; Q[mi][1] = fmaf(v2,v2,fmaf(v3,v3,Q[mi][1]));
            }
        #pragma unroll
        for (int mi = 0; mi < 2; mi++)
            #pragma unroll
            for (int h = 0; h < 2; h++) {
                float s = S[mi][h], q = Q[mi][h];
                s += __shfl_xor_sync(~0u, s, 1); s += __shfl_xor_sync(~0u, s, 2);
                q += __shfl_xor_sync(~0u, q, 1); q += __shfl_xor_sync(~0u, q, 2);
                if (tt == 0) {
                    int row = mi*16 + h*8 + g;
                    sm[O_SRS + row*8 + wn] = s;
                    sm[O_SRQ + row*8 + wn] = q;
                }
            }
        __syncthreads();
        if (t < 32) {
            float s = 0.f, q = 0.f;
            #pragma unroll
            for (int i = 0; i < 8; i++) { s += sm[O_SRS + t*8 + i]; q += sm[O_SRQ + t*8 + i]; }
            float mu = s * (1.f/256.f);
            sm[O_RS + t] = rsqrtf(fmaf(-mu, mu, q * (1.f/256.f)) + 1e-5f);
            sm[O_MU + t] = mu;
        }
        __syncthreads();
        // LN + SiLU -> h plane
        #pragma unroll
        for (int mi = 0; mi < 2; mi++)
            #pragma unroll
            for (int h = 0; h < 2; h++) {
                int row = mi*16 + h*8 + g;
                float mu = sm[O_MU + row], rs = sm[O_RS + row];
                uint32_t w4[4];
                #pragma unroll
                for (int nt = 0; nt < 4; nt++) {
                    int bc = wn*32 + nt*8 + 2*tt;
                    float h0 = silu(fmaf((ch[mi][nt][2*h]   - mu)*rs, gap[bc],   bep[bc]));
                    float h1 = silu(fmaf((ch[mi][nt][2*h+1] - mu)*rs, gap[bc+1], bep[bc+1]));
                    w4[nt] = packh2(h0, h1);
                }
                ST4(su + (uint32_t)((O_HH + row*144 + wn*16 + tt*4)*4), w4[0], w4[1], w4[2], w4[3]);
            }
        __syncthreads();   // publish h plane

        // GEMM2: D = h @ W2
        #pragma unroll
        for (int mi = 0; mi < 2; mi++)
            #pragma unroll
            for (int nt = 0; nt < 4; nt++)
                #pragma unroll
                for (int e = 0; e < 4; e++) { ch[mi][nt][e] = 0.f; cl[mi][nt][e] = 0.f; }
        gemm_ldg<4>(su, O_HH, g_w2h + lay*32768, g_w2l + lay*32768, ch, cl, wn, g, tt);

        // epilogue2: x = x_old(XH/XL planes) + D + b2; refresh planes
        #pragma unroll
        for (int mi = 0; mi < 2; mi++)
            #pragma unroll
            for (int h = 0; h < 2; h++) {
                int row = mi*16 + h*8 + g;
                uint32_t off = (uint32_t)((row*144 + wn*16 + tt*4)*4);
                uint32_t oh0,oh1,oh2,oh3, ol0,ol1,ol2,ol3;
                LD4(oh0,oh1,oh2,oh3, su + (uint32_t)(O_XH*4) + off);
                LD4(ol0,ol1,ol2,ol3, su + (uint32_t)(O_XL*4) + off);
                uint32_t ohs[4] = {oh0,oh1,oh2,oh3};
                uint32_t ols[4] = {ol0,ol1,ol2,ol3};
                uint32_t nh[4], nl[4];
                #pragma unroll
                for (int nt = 0; nt < 4; nt++) {
                    int bc = wn*32 + nt*8 + 2*tt;
                    float2 xo = __half22float2(*reinterpret_cast<__half2*>(&ohs[nt]));
                    float2 xl = __half22float2(*reinterpret_cast<__half2*>(&ols[nt]));
                    float x0 = fmaf(xl.x, INV2048, xo.x) + fmaf(cl[mi][nt][2*h],   INV2048, ch[mi][nt][2*h])   + b2p[bc];
                    float x1 = fmaf(xl.y, INV2048, xo.y) + fmaf(cl[mi][nt][2*h+1], INV2048, ch[mi][nt][2*h+1]) + b2p[bc + 1];
                    splitx2(x0, x1, nh[nt], nl[nt]);
                }
                ST4(su + (uint32_t)(O_XH*4) + off, nh[0], nh[1], nh[2], nh[3]);
                ST4(su + (uint32_t)(O_XL*4) + off, nl[0], nl[1], nl[2], nl[3]);
            }
        __syncthreads();   // publish refreshed x planes
    }

    // ---- head GEMM: D = x @ out_w1 (N=128) ----
    {
        float ch[2][2][4], cl[2][2][4];
        #pragma unroll
        for (int mi = 0; mi < 2; mi++)
            #pragma unroll
            for (int nt = 0; nt < 2; nt++)
                #pragma unroll
                for (int e = 0; e < 4; e++) { ch[mi][nt][e] = 0.f; cl[mi][nt][e] = 0.f; }
        gemm_ldg<2>(su, O_XH, g_owh, g_owl, ch, cl, wn, g, tt);

        __syncthreads();   // XH reads done before HH region reused as fp32 y1
        float* y1f = sm + O_HH;
        #pragma unroll
        for (int mi = 0; mi < 2; mi++)
            #pragma unroll
            for (int h = 0; h < 2; h++) {
                int row = mi*16 + h*8 + g;
                #pragma unroll
                for (int nt = 0; nt < 2; nt++) {
                    int bc = wn*16 + nt*8 + 2*tt;
                    float v0 = fmaf(cl[mi][nt][2*h],   INV2048, ch[mi][nt][2*h])   + out_b1[bc];
                    float v1 = fmaf(cl[mi][nt][2*h+1], INV2048, ch[mi][nt][2*h+1]) + out_b1[bc+1];
                    y1f[row*132 + bc]     = silu(v0);
                    y1f[row*132 + bc + 1] = silu(v1);
                }
            }
    }
    __syncthreads();

    // ---- final: score = y1 @ out_w2 + out_b2 (128 -> 3, fp32) ----
    if (t < 96) {
        int rr = t / 3, p = t - rr*3;
        float a = out_b2[p];
        const float* y = sm + O_HH + rr*132;
        #pragma unroll 8
        for (int k = 0; k < 128; k++) a = fmaf(y[k], out_w2[k*3 + p], a);
        out[(size_t)((b*NN + row0 + rr)*3 + p)] = a;
    }
}

// =====================================================================
extern "C" void kernel_launch(void* const* d_in, const int* in_sizes, int n_in,
                              void* d_out, int out_size)
{
    const float* noisy  = (const float*)d_in[0];
    const float* target = (const float*)d_in[1];
    const int*   tsteps = (const int*)  d_in[2];
    const float* te_w1  = (const float*)d_in[3];
    const float* te_b1  = (const float*)d_in[4];
    const float* te_w2  = (const float*)d_in[5];
    const float* te_b2  = (const float*)d_in[6];
    const float* tp_w   = (const float*)d_in[7];
    const float* tp_b   = (const float*)d_in[8];
    const float* in_w   = (const float*)d_in[9];
    const float* in_b   = (const float*)d_in[10];
    const float* ly_w1  = (const float*)d_in[11];
    const float* ly_b1  = (const float*)d_in[12];
    const float* ly_g   = (const float*)d_in[13];
    const float* ly_be  = (const float*)d_in[14];
    const float* ly_w2  = (const float*)d_in[15];
    const float* ly_b2  = (const float*)d_in[16];
    const float* out_w1 = (const float*)d_in[17];
    const float* out_b1 = (const float*)d_in[18];
    const float* out_w2 = (const float*)d_in[19];
    const float* out_b2 = (const float*)d_in[20];
    float* out = (float*)d_out;

    cudaFuncSetAttribute(mlp_f16, cudaFuncAttributeMaxDynamicSharedMemorySize, SMEM_BYTES);

    prep_kernel<<<PREP_TOTAL, 256>>>(noisy, target, tsteps,
                                     te_w1, te_b1, te_w2, te_b2, tp_w, tp_b,
                                     ly_w1, ly_w2, out_w1);
    mlp_f16<<<1024, 256, SMEM_BYTES>>>(noisy, target, in_w, in_b,
                                       ly_b1, ly_g, ly_be, ly_b2,
                                       out_b1, out_w2, out_b2, out);
}